// round 10
// baseline (speedup 1.0000x reference)
#include <cuda_runtime.h>
#include <math.h>
#include <stdint.h>

#define BB   2
#define TT   1024
#define HH   1024
#define NHD  16
#define NKVH 4
#define HDD  64
#define NE   64
#define TOPK 8
#define NI   512
#define NTOK (BB*TT)   // 2048
#define MT   128       // MoE token tile

typedef unsigned long long ull;

// ---------------- f32x2 helpers (attention) ----------------
__device__ __forceinline__ ull pk2(float a, float b) {
    ull r; asm("mov.b64 %0,{%1,%2};" : "=l"(r) : "f"(a), "f"(b)); return r;
}
__device__ __forceinline__ void fma2(ull& d, ull a, ull b) {
    asm("fma.rn.f32x2 %0,%1,%2,%0;" : "+l"(d) : "l"(a), "l"(b));
}
__device__ __forceinline__ void mul2(ull& d, ull a) {
    asm("mul.rn.f32x2 %0,%0,%1;" : "+l"(d) : "l"(a));
}
__device__ __forceinline__ float2 up2(ull v) {
    float2 f; asm("mov.b64 {%0,%1},%2;" : "=f"(f.x), "=f"(f.y) : "l"(v)); return f;
}

// ---------------- tf32 mma helpers ----------------
__device__ __forceinline__ void mma_tf32(float* d, const uint32_t* a, const uint32_t* b) {
    asm volatile(
        "mma.sync.aligned.m16n8k8.row.col.f32.tf32.tf32.f32 "
        "{%0,%1,%2,%3}, {%4,%5,%6,%7}, {%8,%9}, {%0,%1,%2,%3};"
        : "+f"(d[0]), "+f"(d[1]), "+f"(d[2]), "+f"(d[3])
        : "r"(a[0]), "r"(a[1]), "r"(a[2]), "r"(a[3]), "r"(b[0]), "r"(b[1]));
}
__device__ __forceinline__ uint32_t cvta_s(const void* p) {
    return (uint32_t)__cvta_generic_to_shared(p);
}
__device__ __forceinline__ void cp16(uint32_t s, const void* g) {
    asm volatile("cp.async.cg.shared.global [%0], [%1], 16;" :: "r"(s), "l"(g));
}
#define CP_COMMIT asm volatile("cp.async.commit_group;")
#define CP_WAIT0  asm volatile("cp.async.wait_group 0;")
#define CP_WAIT1  asm volatile("cp.async.wait_group 1;")

// ---------------- scratch (device globals) ----------
__device__ float g_h  [NTOK*HH];
__device__ float g_q  [NTOK*NHD*HDD];
__device__ float g_k  [NTOK*NKVH*HDD];
__device__ float g_v  [NTOK*NKVH*HDD];
__device__ float g_att[NTOK*NHD*HDD];
__device__ float g_f  [NTOK*HH];
__device__ float g_y  [(size_t)NTOK*TOPK*HH];   // 64MB
__device__ float g_G  [(size_t)NTOK*TOPK*NI];   // 32MB: silu(gate)*up per slot
__device__ int   g_cnt[NE];
__device__ int   g_tok[NE*NTOK];
__device__ float g_scr[NE*NTOK];
__device__ int   g_slt[NE*NTOK];

// ---------------- rmsnorm ----------------
__global__ void rmsnorm_k(const float* __restrict__ x, const float* __restrict__ w,
                          float* __restrict__ o) {
    int row = blockIdx.x;
    const float* xr = x + (size_t)row * HH;
    float ss = 0.f;
    for (int i = threadIdx.x; i < HH; i += 256) { float v = xr[i]; ss += v * v; }
    __shared__ float red[256];
    red[threadIdx.x] = ss; __syncthreads();
    for (int s = 128; s > 0; s >>= 1) {
        if (threadIdx.x < s) red[threadIdx.x] += red[threadIdx.x + s];
        __syncthreads();
    }
    float inv = rsqrtf(red[0] * (1.0f / HH) + 1e-6f);
    float* op = o + (size_t)row * HH;
    for (int i = threadIdx.x; i < HH; i += 256) op[i] = xr[i] * inv * w[i];
}

// ======== 128x128 tf32 MMA GEMM core (QKV / Wo) ========
__device__ __forceinline__ void stageAB(int tid, int buf, int k0,
    const float* __restrict__ Ab, int K, const float* __restrict__ Bb, int N,
    float (*As)[128][20], float (*Bs)[16][136]) {
    #pragma unroll
    for (int i = 0; i < 2; i++) {
        int slot = tid + i * 256;
        int row = slot >> 2, seg = slot & 3;
        cp16(cvta_s(&As[buf][row][seg * 4]), Ab + (size_t)row * K + k0 + seg * 4);
    }
    #pragma unroll
    for (int i = 0; i < 2; i++) {
        int slot = tid + i * 256;
        int r = slot >> 5, c4 = (slot & 31) * 4;
        cp16(cvta_s(&Bs[buf][r][c4]), Bb + (size_t)(k0 + r) * N + c4);
    }
}

__device__ __forceinline__ void gemm128_mma(
    const float* __restrict__ Ab, int K, const float* __restrict__ Bb, int N,
    float (*As)[128][20], float (*Bs)[16][136],
    float acc[2][8][4], int tid)
{
    int lane = tid & 31, wid = tid >> 5;
    int wm = (wid & 3) * 32, wn = (wid >> 2) * 64;

    stageAB(tid, 0, 0, Ab, K, Bb, N, As, Bs);
    CP_COMMIT;
    int nit = K >> 4;
    for (int it = 0; it < nit; it++) {
        if (it + 1 < nit) {
            stageAB(tid, (it + 1) & 1, (it + 1) << 4, Ab, K, Bb, N, As, Bs);
            CP_COMMIT; CP_WAIT1;
        } else { CP_WAIT0; }
        __syncthreads();
        const float (*A1)[20]  = As[it & 1];
        const float (*B1)[136] = Bs[it & 1];
        #pragma unroll
        for (int k8 = 0; k8 < 16; k8 += 8) {
            int kk = k8 + (lane & 3);
            uint32_t af[2][4];
            #pragma unroll
            for (int t = 0; t < 2; t++) {
                int r = wm + t * 16 + (lane >> 2);
                af[t][0] = __float_as_uint(A1[r][kk]);
                af[t][1] = __float_as_uint(A1[r + 8][kk]);
                af[t][2] = __float_as_uint(A1[r][kk + 4]);
                af[t][3] = __float_as_uint(A1[r + 8][kk + 4]);
            }
            #pragma unroll
            for (int j = 0; j < 8; j++) {
                int c = wn + j * 8 + (lane >> 2);
                uint32_t bf[2];
                bf[0] = __float_as_uint(B1[kk][c]);
                bf[1] = __float_as_uint(B1[kk + 4][c]);
                mma_tf32(acc[0][j], af[0], bf);
                mma_tf32(acc[1][j], af[1], bf);
            }
        }
        __syncthreads();
    }
}

// ---------------- fused QKV (tf32 mma) ----------------
__global__ __launch_bounds__(256)
void qkv_mma_k(const float* __restrict__ A,
               const float* __restrict__ Wq, const float* __restrict__ Wk,
               const float* __restrict__ Wv,
               float* __restrict__ qo, float* __restrict__ ko, float* __restrict__ vo) {
    __shared__ float As[2][128][20];
    __shared__ float Bs[2][16][136];
    int bx = blockIdx.x;
    const float* Bp; float* O; int N, colb;
    if (bx < 8)       { Bp = Wq; O = qo; N = 1024; colb = bx * 128; }
    else if (bx < 10) { Bp = Wk; O = ko; N = 256;  colb = (bx - 8)  * 128; }
    else              { Bp = Wv; O = vo; N = 256;  colb = (bx - 10) * 128; }

    int tid = threadIdx.x, lane = tid & 31, wid = tid >> 5;
    int wm = (wid & 3) * 32, wn = (wid >> 2) * 64;
    int mbase = blockIdx.y * 128;
    float acc[2][8][4];
    #pragma unroll
    for (int t = 0; t < 2; t++)
        #pragma unroll
        for (int j = 0; j < 8; j++)
            #pragma unroll
            for (int q = 0; q < 4; q++) acc[t][j][q] = 0.f;

    gemm128_mma(A + (size_t)mbase * HH, HH, Bp + colb, N, As, Bs, acc, tid);

    #pragma unroll
    for (int t = 0; t < 2; t++) {
        int r0 = mbase + wm + t * 16 + (lane >> 2);
        #pragma unroll
        for (int j = 0; j < 8; j++) {
            int c = colb + wn + j * 8 + 2 * (lane & 3);
            *(float2*)(O + (size_t)r0 * N + c)       = make_float2(acc[t][j][0], acc[t][j][1]);
            *(float2*)(O + (size_t)(r0 + 8) * N + c) = make_float2(acc[t][j][2], acc[t][j][3]);
        }
    }
}

// ---------------- Wo GEMM + residual (tf32 mma) ----------------
__global__ __launch_bounds__(256)
void wo_mma_k(const float* __restrict__ A, const float* __restrict__ B,
              const float* __restrict__ R, float* __restrict__ C) {
    __shared__ float As[2][128][20];
    __shared__ float Bs[2][16][136];
    int tid = threadIdx.x, lane = tid & 31, wid = tid >> 5;
    int wm = (wid & 3) * 32, wn = (wid >> 2) * 64;
    int mbase = blockIdx.y * 128, nbase = blockIdx.x * 128;
    float acc[2][8][4];
    #pragma unroll
    for (int t = 0; t < 2; t++)
        #pragma unroll
        for (int j = 0; j < 8; j++)
            #pragma unroll
            for (int q = 0; q < 4; q++) acc[t][j][q] = 0.f;

    gemm128_mma(A + (size_t)mbase * HH, HH, B + nbase, HH, As, Bs, acc, tid);

    #pragma unroll
    for (int t = 0; t < 2; t++) {
        int r0 = mbase + wm + t * 16 + (lane >> 2);
        #pragma unroll
        for (int j = 0; j < 8; j++) {
            int c = nbase + wn + j * 8 + 2 * (lane & 3);
            float2 x0 = *(const float2*)(R + (size_t)r0 * HH + c);
            float2 x1 = *(const float2*)(R + (size_t)(r0 + 8) * HH + c);
            *(float2*)(C + (size_t)r0 * HH + c) =
                make_float2(acc[t][j][0] + x0.x, acc[t][j][1] + x0.y);
            *(float2*)(C + (size_t)(r0 + 8) * HH + c) =
                make_float2(acc[t][j][2] + x1.x, acc[t][j][3] + x1.y);
        }
    }
}

// ---------------- RoPE (in-place) ----------------
__global__ void rope_k(float* __restrict__ q, const float* __restrict__ cosp,
                       const float* __restrict__ sinp, int heads, int total) {
    int idx = blockIdx.x * blockDim.x + threadIdx.x;
    if (idx >= total) return;
    int d  = idx & 31;
    int t2 = idx >> 5;
    int hh = t2 % heads;
    int n  = t2 / heads;
    int t  = n & (TT - 1);
    float* p = q + ((size_t)n * heads + hh) * HDD;
    float c1 = cosp[t * HDD + d],      s1 = sinp[t * HDD + d];
    float c2 = cosp[t * HDD + d + 32], s2 = sinp[t * HDD + d + 32];
    float a = p[d], b = p[d + 32];
    p[d]      = a * c1 - b * s1;
    p[d + 32] = b * c2 + a * s2;
}

// ---------------- causal GQA attention (f32x2 online softmax) ----------------
__global__ __launch_bounds__(128)
void attn_k(const float* __restrict__ q, const float* __restrict__ k,
            const float* __restrict__ v, float* __restrict__ o) {
    __shared__ float Ks[64][HDD];
    __shared__ float Vs[64][HDD];
    int bh  = blockIdx.y;
    int b   = bh >> 4;
    int h   = bh & 15;
    int kvh = h >> 2;
    int bx  = gridDim.x - 1 - blockIdx.x;
    int qi  = bx * 128 + threadIdx.x;

    ull q2[32], o2[32];
    const ull* qp = (const ull*)(q + (((size_t)(b * TT + qi)) * NHD + h) * HDD);
    ull sc = pk2(0.125f, 0.125f);
    #pragma unroll
    for (int d = 0; d < 32; d++) { q2[d] = qp[d]; mul2(q2[d], sc); o2[d] = 0ull; }
    float m = -1e30f, l = 0.f;

    int qmax = bx * 128 + 127;
    for (int j0 = 0; j0 <= qmax; j0 += 64) {
        __syncthreads();
        for (int e = threadIdx.x; e < 64 * (HDD / 4); e += 128) {
            int jj = e >> 4;
            int dd = (e & 15) * 4;
            size_t base = (((size_t)(b * TT + j0 + jj)) * NKVH + kvh) * HDD + dd;
            *(float4*)&Ks[jj][dd] = *(const float4*)(k + base);
            *(float4*)&Vs[jj][dd] = *(const float4*)(v + base);
        }
        __syncthreads();
        int jend = qi - j0 + 1;
        if (jend > 64) jend = 64;
        for (int jj = 0; jj < jend; jj++) {
            const ull* kr = (const ull*)Ks[jj];
            ull sA = 0ull, sB = 0ull, sC = 0ull, sD = 0ull;
            #pragma unroll
            for (int d = 0; d < 32; d += 4) {
                fma2(sA, q2[d],     kr[d]);
                fma2(sB, q2[d + 1], kr[d + 1]);
                fma2(sC, q2[d + 2], kr[d + 2]);
                fma2(sD, q2[d + 3], kr[d + 3]);
            }
            float2 fA = up2(sA), fB = up2(sB), fC = up2(sC), fD = up2(sD);
            float s = (fA.x + fA.y) + (fB.x + fB.y) + (fC.x + fC.y) + (fD.x + fD.y);
            if (s > m) {
                float fexp = __expf(m - s);
                ull f2 = pk2(fexp, fexp);
                l *= fexp;
                #pragma unroll
                for (int d = 0; d < 32; d++) mul2(o2[d], f2);
                m = s;
            }
            float p = __expf(s - m);
            l += p;
            ull p2 = pk2(p, p);
            const ull* vr = (const ull*)Vs[jj];
            #pragma unroll
            for (int d = 0; d < 32; d++) fma2(o2[d], p2, vr[d]);
        }
    }
    float invl = 1.f / l;
    ull il2 = pk2(invl, invl);
    ull* op = (ull*)(o + (((size_t)(b * TT + qi)) * NHD + h) * HDD);
    #pragma unroll
    for (int d = 0; d < 32; d++) { mul2(o2[d], il2); op[d] = o2[d]; }
}

// ---------------- router SGEMM (fp32, N=64) ----------------
__global__ __launch_bounds__(256)
void sgemm_k(const float* __restrict__ A, const float* __restrict__ B,
             float* __restrict__ C, int M, int N, int K) {
    __shared__ ull   As2[16][64];
    __shared__ float Bs[16][64];
    int tid = threadIdx.x;
    int tx = tid & 15, ty = tid >> 4;
    const float* Ab = A + (size_t)blockIdx.y * 64 * K;
    const float* Bb = B + (size_t)blockIdx.x * 64;
    ull acc[4][2];
    #pragma unroll
    for (int i = 0; i < 4; i++) { acc[i][0] = 0ull; acc[i][1] = 0ull; }

    for (int k0 = 0; k0 < K; k0 += 16) {
        #pragma unroll
        for (int l = 0; l < 4; l++) {
            int idx = tid + l * 256;
            int m = idx >> 4, k = idx & 15;
            float v = Ab[(size_t)m * K + k0 + k];
            As2[k][m] = pk2(v, v);
        }
        #pragma unroll
        for (int l = 0; l < 4; l++) {
            int idx = tid + l * 256;
            int k = idx >> 6, n = idx & 63;
            Bs[k][n] = Bb[(size_t)(k0 + k) * N + n];
        }
        __syncthreads();
        #pragma unroll
        for (int k = 0; k < 16; k++) {
            const ull* brow = (const ull*)Bs[k];
            ull b0 = brow[tx * 2], b1 = brow[tx * 2 + 1];
            #pragma unroll
            for (int i = 0; i < 4; i++) {
                ull a2 = As2[k][ty * 4 + i];
                fma2(acc[i][0], a2, b0);
                fma2(acc[i][1], a2, b1);
            }
        }
        __syncthreads();
    }
    #pragma unroll
    for (int i = 0; i < 4; i++) {
        int m = blockIdx.y * 64 + ty * 4 + i;
        int nb = blockIdx.x * 64 + tx * 4;
        float2 c0 = up2(acc[i][0]), c1 = up2(acc[i][1]);
        *(float4*)(C + (size_t)m * N + nb) = make_float4(c0.x, c0.y, c1.x, c1.y);
    }
}

// ---------------- router top-8 select + expert scatter ----------------
__global__ void zero_cnt_k() {
    if (threadIdx.x < NE) g_cnt[threadIdx.x] = 0;
}

__global__ void topk_k(const float* __restrict__ logits) {
    int n = blockIdx.x * blockDim.x + threadIdx.x;
    if (n >= NTOK) return;
    float lg[NE];
    for (int e = 0; e < NE; e++) lg[e] = logits[(size_t)n * NE + e];
    int   ids[TOPK];
    float vals[TOPK];
    for (int kk = 0; kk < TOPK; kk++) {
        int best = 0; float bv = lg[0];
        for (int e = 1; e < NE; e++) if (lg[e] > bv) { bv = lg[e]; best = e; }
        ids[kk] = best; vals[kk] = bv; lg[best] = -1e30f;
    }
    float mx = vals[0], sum = 0.f;
    for (int kk = 0; kk < TOPK; kk++) { vals[kk] = __expf(vals[kk] - mx); sum += vals[kk]; }
    float inv = 1.f / sum;
    for (int kk = 0; kk < TOPK; kk++) {
        int e = ids[kk];
        int p = atomicAdd(&g_cnt[e], 1);
        g_tok[e * NTOK + p] = n;
        g_scr[e * NTOK + p] = vals[kk] * inv;
        g_slt[e * NTOK + p] = n * TOPK + kk;
    }
}

// ======== MoE phase 1: gate+up+silu -> G. 128-token x 128-inter tiles ========
// grid (tile, expert, NI/128). dyn smem floats:
//  Ast[2][128][20] @0 (5120) | Bg/Bu Wt[2][2*16*136] @5120 (8704) | toks @13824 | slts @13952
#define MOE1_SMEM ((13824 + 256) * 4)

__global__ __launch_bounds__(256, 1)
void moe1_k(const float* __restrict__ f, const float* __restrict__ Wg,
            const float* __restrict__ Wu, float* __restrict__ G) {
    extern __shared__ float sm[];
    float (*Ast)[128][20] = (float(*)[128][20])sm;
    float* Wt   = sm + 5120;             // [2][4352]: per buf Bg[16][136], Bu[16][136]
    int*   toks = (int*)(sm + 13824);
    int*   slts = (int*)(sm + 13952);

    int e  = blockIdx.y;
    int nt = g_cnt[e];
    int t0 = blockIdx.x * MT;
    if (t0 >= nt) return;
    int nsl = blockIdx.z * 128;          // inter-col slice base

    int tid = threadIdx.x, lane = tid & 31, wid = tid >> 5;
    int wm = (wid & 3) * 32, wn = (wid >> 2) * 64;

    #pragma unroll
    for (int i = 0; i < 1; i++) {
        if (tid < MT) {
            int ti = t0 + tid;
            toks[tid] = (ti < nt) ? g_tok[e * NTOK + ti] : 0;
            slts[tid] = (ti < nt) ? g_slt[e * NTOK + ti] : -1;
        }
    }
    __syncthreads();

    const float* Wge = Wg + (size_t)e * HH * NI + nsl;
    const float* Wue = Wu + (size_t)e * HH * NI + nsl;

    float ag[2][8][4], au[2][8][4];
    #pragma unroll
    for (int t = 0; t < 2; t++)
        #pragma unroll
        for (int j = 0; j < 8; j++)
            #pragma unroll
            for (int q = 0; q < 4; q++) { ag[t][j][q] = 0.f; au[t][j][q] = 0.f; }

    #define M1STAGE(buf, k0) do {                                               \
        _Pragma("unroll")                                                       \
        for (int i = 0; i < 2; i++) {                                           \
            int s = tid + i * 256;                                              \
            int row = s >> 2, seg = s & 3;                                      \
            cp16(cvta_s(&Ast[buf][row][seg * 4]),                               \
                 f + (size_t)toks[row] * HH + (k0) + seg * 4);                  \
        }                                                                       \
        float* bg = Wt + (buf) * 4352;                                          \
        float* bu = bg + 2176;                                                  \
        _Pragma("unroll")                                                       \
        for (int i = 0; i < 2; i++) {                                           \
            int s = tid + i * 256;                                              \
            int r = s >> 5, c4 = (s & 31) * 4;                                  \
            cp16(cvta_s(bg + r * 136 + c4), Wge + (size_t)((k0) + r) * NI + c4);\
            cp16(cvta_s(bu + r * 136 + c4), Wue + (size_t)((k0) + r) * NI + c4);\
        }                                                                       \
    } while (0)

    M1STAGE(0, 0); CP_COMMIT;
    for (int it = 0; it < 64; it++) {
        if (it + 1 < 64) { M1STAGE((it + 1) & 1, (it + 1) << 4); CP_COMMIT; CP_WAIT1; }
        else { CP_WAIT0; }
        __syncthreads();
        int buf = it & 1;
        const float (*A1)[20] = Ast[buf];
        const float* bg = Wt + buf * 4352;
        const float* bu = bg + 2176;
        #pragma unroll
        for (int k8 = 0; k8 < 16; k8 += 8) {
            int kk = k8 + (lane & 3);
            uint32_t af[2][4];
            #pragma unroll
            for (int t = 0; t < 2; t++) {
                int r = wm + t * 16 + (lane >> 2);
                af[t][0] = __float_as_uint(A1[r][kk]);
                af[t][1] = __float_as_uint(A1[r + 8][kk]);
                af[t][2] = __float_as_uint(A1[r][kk + 4]);
                af[t][3] = __float_as_uint(A1[r + 8][kk + 4]);
            }
            #pragma unroll
            for (int j = 0; j < 8; j++) {
                int c = wn + j * 8 + (lane >> 2);
                uint32_t bfg[2], bfu[2];
                bfg[0] = __float_as_uint(bg[kk * 136 + c]);
                bfg[1] = __float_as_uint(bg[(kk + 4) * 136 + c]);
                bfu[0] = __float_as_uint(bu[kk * 136 + c]);
                bfu[1] = __float_as_uint(bu[(kk + 4) * 136 + c]);
                mma_tf32(ag[0][j], af[0], bfg);
                mma_tf32(ag[1][j], af[1], bfg);
                mma_tf32(au[0][j], af[0], bfu);
                mma_tf32(au[1][j], af[1], bfu);
            }
        }
        __syncthreads();
    }

    // silu(g)*u -> G[slot][nsl + c]
    #pragma unroll
    for (int t = 0; t < 2; t++) {
        int r0 = wm + t * 16 + (lane >> 2);
        int s0 = slts[r0], s1 = slts[r0 + 8];
        #pragma unroll
        for (int j = 0; j < 8; j++) {
            int c = nsl + wn + j * 8 + 2 * (lane & 3);
            float g0 = ag[t][j][0], g1 = ag[t][j][1];
            float g2 = ag[t][j][2], g3 = ag[t][j][3];
            if (s0 >= 0)
                *(float2*)(G + (size_t)s0 * NI + c) = make_float2(
                    g0 / (1.f + __expf(-g0)) * au[t][j][0],
                    g1 / (1.f + __expf(-g1)) * au[t][j][1]);
            if (s1 >= 0)
                *(float2*)(G + (size_t)s1 * NI + c) = make_float2(
                    g2 / (1.f + __expf(-g2)) * au[t][j][2],
                    g3 / (1.f + __expf(-g3)) * au[t][j][3]);
        }
    }
    #undef M1STAGE
}

// ======== MoE phase 2: down-proj. 128-token x 256-out tiles ========
// grid (tile, expert, HH/256). dyn smem floats:
//  Ast[2][128][20] @0 (5120) | Bd Wt[2][16*264] @5120 (8448) | slts @13568 | scs @13696
#define MOE2_SMEM ((13568 + 256) * 4)

__global__ __launch_bounds__(256, 1)
void moe2_k(const float* __restrict__ G, const float* __restrict__ Wd,
            float* __restrict__ y) {
    extern __shared__ float sm[];
    float (*Ast)[128][20] = (float(*)[128][20])sm;
    float* Wt   = sm + 5120;             // [2][4224]: Bd[16][264]
    int*   slts = (int*)(sm + 13568);
    float* scs  = (float*)(sm + 13696);

    int e  = blockIdx.y;
    int nt = g_cnt[e];
    int t0 = blockIdx.x * MT;
    if (t0 >= nt) return;
    int nsl = blockIdx.z * 256;

    int tid = threadIdx.x, lane = tid & 31, wid = tid >> 5;
    int wm = (wid & 3) * 32, wn = (wid >> 2) * 128;

    if (tid < MT) {
        int ti = t0 + tid;
        slts[tid] = (ti < nt) ? g_slt[e * NTOK + ti] : -1;
        scs[tid]  = (ti < nt) ? g_scr[e * NTOK + ti] : 0.f;
    }
    __syncthreads();

    const float* Wde = Wd + (size_t)e * NI * HH + nsl;

    float acc[2][16][4];
    #pragma unroll
    for (int t = 0; t < 2; t++)
        #pragma unroll
        for (int j = 0; j < 16; j++)
            #pragma unroll
            for (int q = 0; q < 4; q++) acc[t][j][q] = 0.f;

    #define M2STAGE(buf, k0) do {                                               \
        _Pragma("unroll")                                                       \
        for (int i = 0; i < 2; i++) {                                           \
            int s = tid + i * 256;                                              \
            int row = s >> 2, seg = s & 3;                                      \
            int sl = slts[row] < 0 ? 0 : slts[row];                             \
            cp16(cvta_s(&Ast[buf][row][seg * 4]),                               \
                 G + (size_t)sl * NI + (k0) + seg * 4);                         \
        }                                                                       \
        float* bd = Wt + (buf) * 4224;                                          \
        _Pragma("unroll")                                                       \
        for (int i = 0; i < 4; i++) {                                           \
            int s = tid + i * 256;                                              \
            int r = s >> 6, c4 = (s & 63) * 4;                                  \
            cp16(cvta_s(bd + r * 264 + c4), Wde + (size_t)((k0) + r) * HH + c4);\
        }                                                                       \
    } while (0)

    M2STAGE(0, 0); CP_COMMIT;
    for (int it = 0; it < 32; it++) {
        if (it + 1 < 32) { M2STAGE((it + 1) & 1, (it + 1) << 4); CP_COMMIT; CP_WAIT1; }
        else { CP_WAIT0; }
        __syncthreads();
        int buf = it & 1;
        const float (*A1)[20] = Ast[buf];
        const float* bd = Wt + buf * 4224;
        #pragma unroll
        for (int k8 = 0; k8 < 16; k8 += 8) {
            int kk = k8 + (lane & 3);
            uint32_t af[2][4];
            #pragma unroll
            for (int t = 0; t < 2; t++) {
                int r = wm + t * 16 + (lane >> 2);
                af[t][0] = __float_as_uint(A1[r][kk]);
                af[t][1] = __float_as_uint(A1[r + 8][kk]);
                af[t][2] = __float_as_uint(A1[r][kk + 4]);
                af[t][3] = __float_as_uint(A1[r + 8][kk + 4]);
            }
            #pragma unroll
            for (int j = 0; j < 16; j++) {
                int c = wn + j * 8 + (lane >> 2);
                uint32_t bf[2];
                bf[0] = __float_as_uint(bd[kk * 264 + c]);
                bf[1] = __float_as_uint(bd[(kk + 4) * 264 + c]);
                mma_tf32(acc[0][j], af[0], bf);
                mma_tf32(acc[1][j], af[1], bf);
            }
        }
        __syncthreads();
    }

    #pragma unroll
    for (int t = 0; t < 2; t++) {
        int r0 = wm + t * 16 + (lane >> 2);
        int s0 = slts[r0], s1 = slts[r0 + 8];
        float c0 = scs[r0], c1 = scs[r0 + 8];
        #pragma unroll
        for (int j = 0; j < 16; j++) {
            int c = nsl + wn + j * 8 + 2 * (lane & 3);
            if (s0 >= 0)
                *(float2*)(y + (size_t)s0 * HH + c) =
                    make_float2(c0 * acc[t][j][0], c0 * acc[t][j][1]);
            if (s1 >= 0)
                *(float2*)(y + (size_t)s1 * HH + c) =
                    make_float2(c1 * acc[t][j][2], c1 * acc[t][j][3]);
        }
    }
    #undef M2STAGE
}

// ---------------- gather: out += sum_k y[(n,k)] ----------------
__global__ void gather_k(const float* __restrict__ y, float* __restrict__ out) {
    int n = blockIdx.x;
    int c = threadIdx.x * 4;
    const float* base = y + (size_t)n * TOPK * HH + c;
    float4 a = *(float4*)(out + (size_t)n * HH + c);
    #pragma unroll
    for (int kk = 0; kk < TOPK; kk++) {
        float4 yv = *(const float4*)(base + (size_t)kk * HH);
        a.x += yv.x; a.y += yv.y; a.z += yv.z; a.w += yv.w;
    }
    *(float4*)(out + (size_t)n * HH + c) = a;
}

// ---------------- launch ----------------
extern "C" void kernel_launch(void* const* d_in, const int* in_sizes, int n_in,
                              void* d_out, int out_size) {
    const float* x    = (const float*)d_in[0];
    const float* cosp = (const float*)d_in[1];
    const float* sinp = (const float*)d_in[2];
    const float* ln1w = (const float*)d_in[3];
    const float* ln2w = (const float*)d_in[4];
    const float* Wq   = (const float*)d_in[5];
    const float* Wk   = (const float*)d_in[6];
    const float* Wv   = (const float*)d_in[7];
    const float* Wo   = (const float*)d_in[8];
    const float* Wr   = (const float*)d_in[9];
    const float* Wg   = (const float*)d_in[10];
    const float* Wu   = (const float*)d_in[11];
    const float* Wd   = (const float*)d_in[12];

    float* out    = (float*)d_out;                       // [NTOK, HH]
    float* logits = (float*)d_out + (size_t)NTOK * HH;   // [NTOK, NE]

    float *hb, *qb, *kb, *vb, *ab, *fb, *yb, *Gb;
    cudaGetSymbolAddress((void**)&hb, g_h);
    cudaGetSymbolAddress((void**)&qb, g_q);
    cudaGetSymbolAddress((void**)&kb, g_k);
    cudaGetSymbolAddress((void**)&vb, g_v);
    cudaGetSymbolAddress((void**)&ab, g_att);
    cudaGetSymbolAddress((void**)&fb, g_f);
    cudaGetSymbolAddress((void**)&yb, g_y);
    cudaGetSymbolAddress((void**)&Gb, g_G);

    cudaFuncSetAttribute(moe1_k, cudaFuncAttributeMaxDynamicSharedMemorySize, MOE1_SMEM);
    cudaFuncSetAttribute(moe2_k, cudaFuncAttributeMaxDynamicSharedMemorySize, MOE2_SMEM);

    // 1. rmsnorm1
    rmsnorm_k<<<NTOK, 256>>>(x, ln1w, hb);
    // 2. fused QKV (tf32 mma)
    qkv_mma_k<<<dim3(12, NTOK / 128), 256>>>(hb, Wq, Wk, Wv, qb, kb, vb);
    // 3. RoPE
    {
        int tq = NTOK * NHD * 32;
        rope_k<<<(tq + 255) / 256, 256>>>(qb, cosp, sinp, NHD, tq);
        int tkn = NTOK * NKVH * 32;
        rope_k<<<(tkn + 255) / 256, 256>>>(kb, cosp, sinp, NKVH, tkn);
    }
    // 4. attention
    attn_k<<<dim3(TT / 128, BB * NHD), 128>>>(qb, kb, vb, ab);
    // 5. Wo + residual -> out
    wo_mma_k<<<dim3(HH / 128, NTOK / 128), 256>>>(ab, Wo, x, out);
    // 6. rmsnorm2
    rmsnorm_k<<<NTOK, 256>>>(out, ln2w, fb);
    // 7. router logits (fp32)
    sgemm_k<<<dim3(1, NTOK / 64), 256>>>(fb, Wr, logits, NTOK, NE, HH);
    // 8-9. top-8 + scatter
    zero_cnt_k<<<1, 64>>>();
    topk_k<<<(NTOK + 255) / 256, 256>>>(logits);
    // 10. MoE phase 1: gate+up+silu -> G
    moe1_k<<<dim3(NTOK / MT, NE, NI / 128), 256, MOE1_SMEM>>>(fb, Wg, Wu, Gb);
    // 11. MoE phase 2: down -> y slots
    moe2_k<<<dim3(NTOK / MT, NE, HH / 256), 256, MOE2_SMEM>>>(Gb, Wd, yb);
    // 12. gather slots into out
    gather_k<<<NTOK, 256>>>(yb, out);
}

// round 12
// speedup vs baseline: 1.3155x; 1.3155x over previous
#include <cuda_runtime.h>
#include <math.h>
#include <stdint.h>

#define BB   2
#define TT   1024
#define HH   1024
#define NHD  16
#define NKVH 4
#define HDD  64
#define NE   64
#define TOPK 8
#define NI   512
#define NTOK (BB*TT)   // 2048
#define MT   32        // MoE token tile

typedef unsigned long long ull;

// ---------------- f32x2 helpers ----------------
__device__ __forceinline__ ull pk2(float a, float b) {
    ull r; asm("mov.b64 %0,{%1,%2};" : "=l"(r) : "f"(a), "f"(b)); return r;
}
__device__ __forceinline__ void fma2(ull& d, ull a, ull b) {
    asm("fma.rn.f32x2 %0,%1,%2,%0;" : "+l"(d) : "l"(a), "l"(b));
}
__device__ __forceinline__ float2 up2(ull v) {
    float2 f; asm("mov.b64 {%0,%1},%2;" : "=f"(f.x), "=f"(f.y) : "l"(v)); return f;
}

// ---------------- tf32 mma helpers ----------------
__device__ __forceinline__ void mma_tf32(float* d, const uint32_t* a, const uint32_t* b) {
    asm volatile(
        "mma.sync.aligned.m16n8k8.row.col.f32.tf32.tf32.f32 "
        "{%0,%1,%2,%3}, {%4,%5,%6,%7}, {%8,%9}, {%0,%1,%2,%3};"
        : "+f"(d[0]), "+f"(d[1]), "+f"(d[2]), "+f"(d[3])
        : "r"(a[0]), "r"(a[1]), "r"(a[2]), "r"(a[3]), "r"(b[0]), "r"(b[1]));
}
__device__ __forceinline__ uint32_t cvta_s(const void* p) {
    return (uint32_t)__cvta_generic_to_shared(p);
}
__device__ __forceinline__ void cp16(uint32_t s, const void* g) {
    asm volatile("cp.async.cg.shared.global [%0], [%1], 16;" :: "r"(s), "l"(g));
}
#define CP_COMMIT asm volatile("cp.async.commit_group;")
#define CP_WAIT0  asm volatile("cp.async.wait_group 0;")
#define CP_WAIT1  asm volatile("cp.async.wait_group 1;")

// ---------------- scratch (device globals) ----------
__device__ float g_h  [NTOK*HH];
__device__ float g_q  [NTOK*NHD*HDD];
__device__ float g_k  [NTOK*NKVH*HDD];
__device__ float g_v  [NTOK*NKVH*HDD];
__device__ float g_att[NTOK*NHD*HDD];
__device__ float g_f  [NTOK*HH];
__device__ float g_y  [(size_t)NTOK*TOPK*HH];
__device__ int   g_cnt[NE];
__device__ int   g_tok[NE*NTOK];
__device__ float g_scr[NE*NTOK];
__device__ int   g_slt[NE*NTOK];

// ---------------- rmsnorm ----------------
__global__ void rmsnorm_k(const float* __restrict__ x, const float* __restrict__ w,
                          float* __restrict__ o) {
    int row = blockIdx.x;
    const float* xr = x + (size_t)row * HH;
    float ss = 0.f;
    for (int i = threadIdx.x; i < HH; i += 256) { float v = xr[i]; ss += v * v; }
    __shared__ float red[256];
    red[threadIdx.x] = ss; __syncthreads();
    for (int s = 128; s > 0; s >>= 1) {
        if (threadIdx.x < s) red[threadIdx.x] += red[threadIdx.x + s];
        __syncthreads();
    }
    float inv = rsqrtf(red[0] * (1.0f / HH) + 1e-6f);
    float* op = o + (size_t)row * HH;
    for (int i = threadIdx.x; i < HH; i += 256) op[i] = xr[i] * inv * w[i];
}

// ======== 128x128 tf32 MMA GEMM core (QKV / Wo) ========
__device__ __forceinline__ void stageAB(int tid, int buf, int k0,
    const float* __restrict__ Ab, int K, const float* __restrict__ Bb, int N,
    float (*As)[128][20], float (*Bs)[16][136]) {
    #pragma unroll
    for (int i = 0; i < 2; i++) {
        int slot = tid + i * 256;
        int row = slot >> 2, seg = slot & 3;
        cp16(cvta_s(&As[buf][row][seg * 4]), Ab + (size_t)row * K + k0 + seg * 4);
    }
    #pragma unroll
    for (int i = 0; i < 2; i++) {
        int slot = tid + i * 256;
        int r = slot >> 5, c4 = (slot & 31) * 4;
        cp16(cvta_s(&Bs[buf][r][c4]), Bb + (size_t)(k0 + r) * N + c4);
    }
}

__device__ __forceinline__ void gemm128_mma(
    const float* __restrict__ Ab, int K, const float* __restrict__ Bb, int N,
    float (*As)[128][20], float (*Bs)[16][136],
    float acc[2][8][4], int tid)
{
    int lane = tid & 31, wid = tid >> 5;
    int wm = (wid & 3) * 32, wn = (wid >> 2) * 64;

    stageAB(tid, 0, 0, Ab, K, Bb, N, As, Bs);
    CP_COMMIT;
    int nit = K >> 4;
    for (int it = 0; it < nit; it++) {
        if (it + 1 < nit) {
            stageAB(tid, (it + 1) & 1, (it + 1) << 4, Ab, K, Bb, N, As, Bs);
            CP_COMMIT; CP_WAIT1;
        } else { CP_WAIT0; }
        __syncthreads();
        const float (*A1)[20]  = As[it & 1];
        const float (*B1)[136] = Bs[it & 1];
        #pragma unroll
        for (int k8 = 0; k8 < 16; k8 += 8) {
            int kk = k8 + (lane & 3);
            uint32_t af[2][4];
            #pragma unroll
            for (int t = 0; t < 2; t++) {
                int r = wm + t * 16 + (lane >> 2);
                af[t][0] = __float_as_uint(A1[r][kk]);
                af[t][1] = __float_as_uint(A1[r + 8][kk]);
                af[t][2] = __float_as_uint(A1[r][kk + 4]);
                af[t][3] = __float_as_uint(A1[r + 8][kk + 4]);
            }
            #pragma unroll
            for (int j = 0; j < 8; j++) {
                int c = wn + j * 8 + (lane >> 2);
                uint32_t bf[2];
                bf[0] = __float_as_uint(B1[kk][c]);
                bf[1] = __float_as_uint(B1[kk + 4][c]);
                mma_tf32(acc[0][j], af[0], bf);
                mma_tf32(acc[1][j], af[1], bf);
            }
        }
        __syncthreads();
    }
}

// ---------------- fused QKV (tf32 mma) ----------------
__global__ __launch_bounds__(256)
void qkv_mma_k(const float* __restrict__ A,
               const float* __restrict__ Wq, const float* __restrict__ Wk,
               const float* __restrict__ Wv,
               float* __restrict__ qo, float* __restrict__ ko, float* __restrict__ vo) {
    __shared__ float As[2][128][20];
    __shared__ float Bs[2][16][136];
    int bx = blockIdx.x;
    const float* Bp; float* O; int N, colb;
    if (bx < 8)       { Bp = Wq; O = qo; N = 1024; colb = bx * 128; }
    else if (bx < 10) { Bp = Wk; O = ko; N = 256;  colb = (bx - 8)  * 128; }
    else              { Bp = Wv; O = vo; N = 256;  colb = (bx - 10) * 128; }

    int tid = threadIdx.x, lane = tid & 31, wid = tid >> 5;
    int wm = (wid & 3) * 32, wn = (wid >> 2) * 64;
    int mbase = blockIdx.y * 128;
    float acc[2][8][4];
    #pragma unroll
    for (int t = 0; t < 2; t++)
        #pragma unroll
        for (int j = 0; j < 8; j++)
            #pragma unroll
            for (int q = 0; q < 4; q++) acc[t][j][q] = 0.f;

    gemm128_mma(A + (size_t)mbase * HH, HH, Bp + colb, N, As, Bs, acc, tid);

    #pragma unroll
    for (int t = 0; t < 2; t++) {
        int r0 = mbase + wm + t * 16 + (lane >> 2);
        #pragma unroll
        for (int j = 0; j < 8; j++) {
            int c = colb + wn + j * 8 + 2 * (lane & 3);
            *(float2*)(O + (size_t)r0 * N + c)       = make_float2(acc[t][j][0], acc[t][j][1]);
            *(float2*)(O + (size_t)(r0 + 8) * N + c) = make_float2(acc[t][j][2], acc[t][j][3]);
        }
    }
}

// ---------------- Wo GEMM + residual (tf32 mma) ----------------
__global__ __launch_bounds__(256)
void wo_mma_k(const float* __restrict__ A, const float* __restrict__ B,
              const float* __restrict__ R, float* __restrict__ C) {
    __shared__ float As[2][128][20];
    __shared__ float Bs[2][16][136];
    int tid = threadIdx.x, lane = tid & 31, wid = tid >> 5;
    int wm = (wid & 3) * 32, wn = (wid >> 2) * 64;
    int mbase = blockIdx.y * 128, nbase = blockIdx.x * 128;
    float acc[2][8][4];
    #pragma unroll
    for (int t = 0; t < 2; t++)
        #pragma unroll
        for (int j = 0; j < 8; j++)
            #pragma unroll
            for (int q = 0; q < 4; q++) acc[t][j][q] = 0.f;

    gemm128_mma(A + (size_t)mbase * HH, HH, B + nbase, HH, As, Bs, acc, tid);

    #pragma unroll
    for (int t = 0; t < 2; t++) {
        int r0 = mbase + wm + t * 16 + (lane >> 2);
        #pragma unroll
        for (int j = 0; j < 8; j++) {
            int c = nbase + wn + j * 8 + 2 * (lane & 3);
            float2 x0 = *(const float2*)(R + (size_t)r0 * HH + c);
            float2 x1 = *(const float2*)(R + (size_t)(r0 + 8) * HH + c);
            *(float2*)(C + (size_t)r0 * HH + c) =
                make_float2(acc[t][j][0] + x0.x, acc[t][j][1] + x0.y);
            *(float2*)(C + (size_t)(r0 + 8) * HH + c) =
                make_float2(acc[t][j][2] + x1.x, acc[t][j][3] + x1.y);
        }
    }
}

// ---------------- RoPE (in-place) ----------------
__global__ void rope_k(float* __restrict__ q, const float* __restrict__ cosp,
                       const float* __restrict__ sinp, int heads, int total) {
    int idx = blockIdx.x * blockDim.x + threadIdx.x;
    if (idx >= total) return;
    int d  = idx & 31;
    int t2 = idx >> 5;
    int hh = t2 % heads;
    int n  = t2 / heads;
    int t  = n & (TT - 1);
    float* p = q + ((size_t)n * heads + hh) * HDD;
    float c1 = cosp[t * HDD + d],      s1 = sinp[t * HDD + d];
    float c2 = cosp[t * HDD + d + 32], s2 = sinp[t * HDD + d + 32];
    float a = p[d], b = p[d + 32];
    p[d]      = a * c1 - b * s1;
    p[d + 32] = b * c2 + a * s2;
}

// ======== flash attention, tf32 mma ========
// grid (TT/128, BB*NHD), 256 threads = 8 warps; warp w owns q rows [w*16, w*16+16).
// smem floats: Qs[128][68] @0, Ks[64][68] @8704, Vs[64][72] @13056, Ps[8][16][68] @17664
#define ATT_SMEM ((17664 + 8704) * 4)

__global__ __launch_bounds__(256, 1)
void attn_mma_k(const float* __restrict__ q, const float* __restrict__ k,
                const float* __restrict__ v, float* __restrict__ o) {
    extern __shared__ float sm[];
    float (*Qs)[68] = (float(*)[68])sm;
    float (*Ks)[68] = (float(*)[68])(sm + 8704);
    float (*Vs)[72] = (float(*)[72])(sm + 13056);
    float (*Ps)[68] = (float(*)[68])(sm + 17664);   // [8*16][68]

    int bh = blockIdx.y;
    int b = bh >> 4, h = bh & 15, kvh = h >> 2;
    int bx = blockIdx.x;
    int tid = threadIdx.x, lane = tid & 31, wq = tid >> 5;
    int gid = lane >> 2, tig = lane & 3;

    // load Q tile (scaled by 1/8)
    for (int i = tid; i < 128 * 16; i += 256) {
        int r = i >> 4, d4 = (i & 15) * 4;
        float4 val = *(const float4*)(q + (((size_t)(b * TT + bx * 128 + r)) * NHD + h) * HDD + d4);
        val.x *= 0.125f; val.y *= 0.125f; val.z *= 0.125f; val.w *= 0.125f;
        *(float4*)&Qs[r][d4] = val;
    }

    float o_acc[8][4];
    #pragma unroll
    for (int j = 0; j < 8; j++)
        #pragma unroll
        for (int qq = 0; qq < 4; qq++) o_acc[j][qq] = 0.f;
    float m0 = -1e30f, m1 = -1e30f, l0 = 0.f, l1 = 0.f;

    int r0g = bx * 128 + wq * 16 + gid;   // global q row of acc rows [0,1]
    int r1g = r0g + 8;                    // rows [2,3]
    float (*Psw)[68] = Ps + wq * 16;

    int kv_end = (bx + 1) * 128;
    for (int j0 = 0; j0 < kv_end; j0 += 64) {
        __syncthreads();
        for (int i = tid; i < 64 * 16; i += 256) {
            int r = i >> 4, d4 = (i & 15) * 4;
            size_t base = (((size_t)(b * TT + j0 + r)) * NKVH + kvh) * HDD + d4;
            *(float4*)&Ks[r][d4] = *(const float4*)(k + base);
            *(float4*)&Vs[r][d4] = *(const float4*)(v + base);
        }
        __syncthreads();

        // S = Q @ K^T  (16 x 64 per warp)  — FULL HD=64 reduction
        float s[8][4];
        #pragma unroll
        for (int j = 0; j < 8; j++)
            #pragma unroll
            for (int qq = 0; qq < 4; qq++) s[j][qq] = 0.f;
        #pragma unroll
        for (int k8 = 0; k8 < 64; k8 += 8) {
            int kk = k8 + tig;
            uint32_t af[4];
            int r = wq * 16 + gid;
            af[0] = __float_as_uint(Qs[r][kk]);
            af[1] = __float_as_uint(Qs[r + 8][kk]);
            af[2] = __float_as_uint(Qs[r][kk + 4]);
            af[3] = __float_as_uint(Qs[r + 8][kk + 4]);
            #pragma unroll
            for (int j = 0; j < 8; j++) {
                int n = j * 8 + gid;
                uint32_t bf[2];
                bf[0] = __float_as_uint(Ks[n][kk]);
                bf[1] = __float_as_uint(Ks[n][kk + 4]);
                mma_tf32(s[j], af, bf);
            }
        }

        // causal mask (only needed near the diagonal)
        if (j0 + 63 > r0g) {
            #pragma unroll
            for (int j = 0; j < 8; j++) {
                int cg = j0 + j * 8 + 2 * tig;
                if (cg > r0g)     s[j][0] = -1e30f;
                if (cg + 1 > r0g) s[j][1] = -1e30f;
            }
        }
        if (j0 + 63 > r1g) {
            #pragma unroll
            for (int j = 0; j < 8; j++) {
                int cg = j0 + j * 8 + 2 * tig;
                if (cg > r1g)     s[j][2] = -1e30f;
                if (cg + 1 > r1g) s[j][3] = -1e30f;
            }
        }

        // online softmax
        float rm0 = -1e30f, rm1 = -1e30f;
        #pragma unroll
        for (int j = 0; j < 8; j++) {
            rm0 = fmaxf(rm0, fmaxf(s[j][0], s[j][1]));
            rm1 = fmaxf(rm1, fmaxf(s[j][2], s[j][3]));
        }
        #pragma unroll
        for (int off = 1; off <= 2; off <<= 1) {
            rm0 = fmaxf(rm0, __shfl_xor_sync(0xffffffff, rm0, off));
            rm1 = fmaxf(rm1, __shfl_xor_sync(0xffffffff, rm1, off));
        }
        float mn0 = fmaxf(m0, rm0), mn1 = fmaxf(m1, rm1);
        float sc0 = __expf(m0 - mn0), sc1 = __expf(m1 - mn1);
        m0 = mn0; m1 = mn1;

        float rs0 = 0.f, rs1 = 0.f;
        float p[8][4];
        #pragma unroll
        for (int j = 0; j < 8; j++) {
            p[j][0] = __expf(s[j][0] - mn0);
            p[j][1] = __expf(s[j][1] - mn0);
            p[j][2] = __expf(s[j][2] - mn1);
            p[j][3] = __expf(s[j][3] - mn1);
            rs0 += p[j][0] + p[j][1];
            rs1 += p[j][2] + p[j][3];
        }
        #pragma unroll
        for (int off = 1; off <= 2; off <<= 1) {
            rs0 += __shfl_xor_sync(0xffffffff, rs0, off);
            rs1 += __shfl_xor_sync(0xffffffff, rs1, off);
        }
        l0 = l0 * sc0 + rs0;
        l1 = l1 * sc1 + rs1;

        #pragma unroll
        for (int j = 0; j < 8; j++) {
            o_acc[j][0] *= sc0; o_acc[j][1] *= sc0;
            o_acc[j][2] *= sc1; o_acc[j][3] *= sc1;
        }

        // write P to warp smem
        #pragma unroll
        for (int j = 0; j < 8; j++) {
            int c = j * 8 + 2 * tig;
            Psw[gid][c]         = p[j][0];
            Psw[gid][c + 1]     = p[j][1];
            Psw[gid + 8][c]     = p[j][2];
            Psw[gid + 8][c + 1] = p[j][3];
        }
        __syncwarp();

        // O += P @ V
        #pragma unroll
        for (int k8 = 0; k8 < 64; k8 += 8) {
            int kk = k8 + tig;
            uint32_t af[4];
            af[0] = __float_as_uint(Psw[gid][kk]);
            af[1] = __float_as_uint(Psw[gid + 8][kk]);
            af[2] = __float_as_uint(Psw[gid][kk + 4]);
            af[3] = __float_as_uint(Psw[gid + 8][kk + 4]);
            #pragma unroll
            for (int j = 0; j < 8; j++) {
                int n = j * 8 + gid;
                uint32_t bf[2];
                bf[0] = __float_as_uint(Vs[kk][n]);
                bf[1] = __float_as_uint(Vs[kk + 4][n]);
                mma_tf32(o_acc[j], af, bf);
            }
        }
    }

    float i0 = 1.f / l0, i1 = 1.f / l1;
    #pragma unroll
    for (int j = 0; j < 8; j++) {
        int c = j * 8 + 2 * tig;
        *(float2*)(o + (((size_t)(b * TT + r0g)) * NHD + h) * HDD + c) =
            make_float2(o_acc[j][0] * i0, o_acc[j][1] * i0);
        *(float2*)(o + (((size_t)(b * TT + r1g)) * NHD + h) * HDD + c) =
            make_float2(o_acc[j][2] * i1, o_acc[j][3] * i1);
    }
}

// ---------------- router SGEMM (fp32, N=64) ----------------
__global__ __launch_bounds__(256)
void sgemm_k(const float* __restrict__ A, const float* __restrict__ B,
             float* __restrict__ C, int M, int N, int K) {
    __shared__ ull   As2[16][64];
    __shared__ float Bs[16][64];
    int tid = threadIdx.x;
    int tx = tid & 15, ty = tid >> 4;
    const float* Ab = A + (size_t)blockIdx.y * 64 * K;
    const float* Bb = B + (size_t)blockIdx.x * 64;
    ull acc[4][2];
    #pragma unroll
    for (int i = 0; i < 4; i++) { acc[i][0] = 0ull; acc[i][1] = 0ull; }

    for (int k0 = 0; k0 < K; k0 += 16) {
        #pragma unroll
        for (int l = 0; l < 4; l++) {
            int idx = tid + l * 256;
            int m = idx >> 4, kk = idx & 15;
            float vv = Ab[(size_t)m * K + k0 + kk];
            As2[kk][m] = pk2(vv, vv);
        }
        #pragma unroll
        for (int l = 0; l < 4; l++) {
            int idx = tid + l * 256;
            int kk = idx >> 6, n = idx & 63;
            Bs[kk][n] = Bb[(size_t)(k0 + kk) * N + n];
        }
        __syncthreads();
        #pragma unroll
        for (int kk = 0; kk < 16; kk++) {
            const ull* brow = (const ull*)Bs[kk];
            ull b0 = brow[tx * 2], b1 = brow[tx * 2 + 1];
            #pragma unroll
            for (int i = 0; i < 4; i++) {
                ull a2 = As2[kk][ty * 4 + i];
                fma2(acc[i][0], a2, b0);
                fma2(acc[i][1], a2, b1);
            }
        }
        __syncthreads();
    }
    #pragma unroll
    for (int i = 0; i < 4; i++) {
        int m = blockIdx.y * 64 + ty * 4 + i;
        int nb = blockIdx.x * 64 + tx * 4;
        float2 c0 = up2(acc[i][0]), c1 = up2(acc[i][1]);
        *(float4*)(C + (size_t)m * N + nb) = make_float4(c0.x, c0.y, c1.x, c1.y);
    }
}

// ---------------- router top-8 select + expert scatter ----------------
__global__ void zero_cnt_k() {
    if (threadIdx.x < NE) g_cnt[threadIdx.x] = 0;
}

__global__ void topk_k(const float* __restrict__ logits) {
    int n = blockIdx.x * blockDim.x + threadIdx.x;
    if (n >= NTOK) return;
    float lg[NE];
    for (int e = 0; e < NE; e++) lg[e] = logits[(size_t)n * NE + e];
    int   ids[TOPK];
    float vals[TOPK];
    for (int kk = 0; kk < TOPK; kk++) {
        int best = 0; float bv = lg[0];
        for (int e = 1; e < NE; e++) if (lg[e] > bv) { bv = lg[e]; best = e; }
        ids[kk] = best; vals[kk] = bv; lg[best] = -1e30f;
    }
    float mx = vals[0], sum = 0.f;
    for (int kk = 0; kk < TOPK; kk++) { vals[kk] = __expf(vals[kk] - mx); sum += vals[kk]; }
    float inv = 1.f / sum;
    for (int kk = 0; kk < TOPK; kk++) {
        int e = ids[kk];
        int p = atomicAdd(&g_cnt[e], 1);
        g_tok[e * NTOK + p] = n;
        g_scr[e * NTOK + p] = vals[kk] * inv;
        g_slt[e * NTOK + p] = n * TOPK + kk;
    }
}

// ======== MoE: tf32 mma, 32-token tiles, 2-phase, cp.async pipelined ========
#define MOE_SMEM_FLOATS (51072 + 96)

__global__ __launch_bounds__(256, 1)
void moe_mma_k(const float* __restrict__ f, const float* __restrict__ Wg,
               const float* __restrict__ Wu, const float* __restrict__ Wd,
               float* __restrict__ y) {
    extern __shared__ float sm[];
    float (*Ast)[32][20] = (float(*)[32][20])sm;
    float (*Gs)[516]     = (float(*)[516])(sm + 1280);
    float* Wt            = sm + 17792;           // [2][16640]
    int*   toks = (int*)(sm + 51072);
    float* scs  = (float*)(sm + 51072 + 32);
    int*   slts = (int*)(sm + 51072 + 64);

    int e  = blockIdx.y;
    int nt = g_cnt[e];
    int t0 = blockIdx.x * MT;
    if (t0 >= nt) return;

    int tid = threadIdx.x, lane = tid & 31, wid = tid >> 5;
    if (tid < MT) {
        int ti = t0 + tid;
        toks[tid] = (ti < nt) ? g_tok[e * NTOK + ti] : 0;
        scs[tid]  = (ti < nt) ? g_scr[e * NTOK + ti] : 0.f;
        slts[tid] = (ti < nt) ? g_slt[e * NTOK + ti] : -1;
    }
    __syncthreads();

    const float* Wge = Wg + (size_t)e * HH * NI;
    const float* Wue = Wu + (size_t)e * HH * NI;
    const float* Wde = Wd + (size_t)e * NI * HH;

    // ---------- phase 1: gate + up;  C[32, 512] x2, K = 1024 ----------
    float ag[2][8][4], au[2][8][4];
    #pragma unroll
    for (int t = 0; t < 2; t++)
        #pragma unroll
        for (int j = 0; j < 8; j++)
            #pragma unroll
            for (int q = 0; q < 4; q++) { ag[t][j][q] = 0.f; au[t][j][q] = 0.f; }

    #define STAGE1(buf, k0) do {                                              \
        if (tid < 128) {                                                      \
            int tok = tid >> 2, seg = tid & 3;                                \
            cp16(cvta_s(&Ast[buf][tok][seg * 4]),                             \
                 f + (size_t)toks[tok] * HH + (k0) + seg * 4);                \
        }                                                                     \
        float* bg = Wt + (buf) * 16640;                                       \
        float* bu = bg + 8320;                                                \
        _Pragma("unroll")                                                     \
        for (int i = 0; i < 8; i++) {                                         \
            int slot = tid + i * 256;                                         \
            int r = slot >> 7, c4 = (slot & 127) * 4;                         \
            cp16(cvta_s(bg + r * 520 + c4), Wge + (size_t)((k0) + r) * NI + c4); \
            cp16(cvta_s(bu + r * 520 + c4), Wue + (size_t)((k0) + r) * NI + c4); \
        }                                                                     \
    } while (0)

    STAGE1(0, 0); CP_COMMIT;
    for (int it = 0; it < 64; it++) {
        if (it + 1 < 64) { STAGE1((it + 1) & 1, (it + 1) << 4); CP_COMMIT; CP_WAIT1; }
        else { CP_WAIT0; }
        __syncthreads();
        int buf = it & 1;
        const float (*A1)[20] = Ast[buf];
        const float* bg = Wt + buf * 16640;
        const float* bu = bg + 8320;
        #pragma unroll
        for (int k8 = 0; k8 < 16; k8 += 8) {
            int kk = k8 + (lane & 3);
            uint32_t af[2][4];
            #pragma unroll
            for (int t = 0; t < 2; t++) {
                int r = t * 16 + (lane >> 2);
                af[t][0] = __float_as_uint(A1[r][kk]);
                af[t][1] = __float_as_uint(A1[r + 8][kk]);
                af[t][2] = __float_as_uint(A1[r][kk + 4]);
                af[t][3] = __float_as_uint(A1[r + 8][kk + 4]);
            }
            #pragma unroll
            for (int j = 0; j < 8; j++) {
                int c = wid * 64 + j * 8 + (lane >> 2);
                uint32_t bfg[2], bfu[2];
                bfg[0] = __float_as_uint(bg[kk * 520 + c]);
                bfg[1] = __float_as_uint(bg[(kk + 4) * 520 + c]);
                bfu[0] = __float_as_uint(bu[kk * 520 + c]);
                bfu[1] = __float_as_uint(bu[(kk + 4) * 520 + c]);
                mma_tf32(ag[0][j], af[0], bfg);
                mma_tf32(ag[1][j], af[1], bfg);
                mma_tf32(au[0][j], af[0], bfu);
                mma_tf32(au[1][j], af[1], bfu);
            }
        }
        __syncthreads();
    }

    // silu(g)*u -> Gs (token-major [32][516])
    #pragma unroll
    for (int t = 0; t < 2; t++) {
        int r0 = t * 16 + (lane >> 2);
        #pragma unroll
        for (int j = 0; j < 8; j++) {
            int c = wid * 64 + j * 8 + 2 * (lane & 3);
            float gv0 = ag[t][j][0], gv1 = ag[t][j][1];
            float gv2 = ag[t][j][2], gv3 = ag[t][j][3];
            Gs[r0][c]         = gv0 / (1.f + __expf(-gv0)) * au[t][j][0];
            Gs[r0][c + 1]     = gv1 / (1.f + __expf(-gv1)) * au[t][j][1];
            Gs[r0 + 8][c]     = gv2 / (1.f + __expf(-gv2)) * au[t][j][2];
            Gs[r0 + 8][c + 1] = gv3 / (1.f + __expf(-gv3)) * au[t][j][3];
        }
    }
    __syncthreads();

    // ---------- phase 2: down;  C[32, 1024], K = 512 ----------
    float acc[2][16][4];
    #pragma unroll
    for (int t = 0; t < 2; t++)
        #pragma unroll
        for (int j = 0; j < 16; j++)
            #pragma unroll
            for (int q = 0; q < 4; q++) acc[t][j][q] = 0.f;

    #define STAGE2(buf, k0) do {                                              \
        float* bd = Wt + (buf) * 16640;                                       \
        _Pragma("unroll")                                                     \
        for (int i = 0; i < 16; i++) {                                        \
            int slot = tid + i * 256;                                         \
            int r = slot >> 8, c4 = (slot & 255) * 4;                         \
            cp16(cvta_s(bd + r * 1032 + c4), Wde + (size_t)((k0) + r) * HH + c4); \
        }                                                                     \
    } while (0)

    STAGE2(0, 0); CP_COMMIT;
    for (int it = 0; it < 32; it++) {
        if (it + 1 < 32) { STAGE2((it + 1) & 1, (it + 1) << 4); CP_COMMIT; CP_WAIT1; }
        else { CP_WAIT0; }
        __syncthreads();
        const float* bd = Wt + (it & 1) * 16640;
        int k0 = it << 4;
        #pragma unroll
        for (int k8 = 0; k8 < 16; k8 += 8) {
            int kk = k0 + k8 + (lane & 3);
            uint32_t af[2][4];
            #pragma unroll
            for (int t = 0; t < 2; t++) {
                int r = t * 16 + (lane >> 2);
                af[t][0] = __float_as_uint(Gs[r][kk]);
                af[t][1] = __float_as_uint(Gs[r + 8][kk]);
                af[t][2] = __float_as_uint(Gs[r][kk + 4]);
                af[t][3] = __float_as_uint(Gs[r + 8][kk + 4]);
            }
            int kl = k8 + (lane & 3);
            #pragma unroll
            for (int j = 0; j < 16; j++) {
                int c = wid * 128 + j * 8 + (lane >> 2);
                uint32_t bf[2];
                bf[0] = __float_as_uint(bd[kl * 1032 + c]);
                bf[1] = __float_as_uint(bd[(kl + 4) * 1032 + c]);
                mma_tf32(acc[0][j], af[0], bf);
                mma_tf32(acc[1][j], af[1], bf);
            }
        }
        __syncthreads();
    }

    #pragma unroll
    for (int t = 0; t < 2; t++) {
        int r0 = t * 16 + (lane >> 2);
        int s0 = slts[r0], s1 = slts[r0 + 8];
        float sc0 = scs[r0], sc1 = scs[r0 + 8];
        #pragma unroll
        for (int j = 0; j < 16; j++) {
            int c = wid * 128 + j * 8 + 2 * (lane & 3);
            if (s0 >= 0)
                *(float2*)(y + (size_t)s0 * HH + c) =
                    make_float2(sc0 * acc[t][j][0], sc0 * acc[t][j][1]);
            if (s1 >= 0)
                *(float2*)(y + (size_t)s1 * HH + c) =
                    make_float2(sc1 * acc[t][j][2], sc1 * acc[t][j][3]);
        }
    }
}

// ---------------- gather: out += sum_k y[(n,k)] ----------------
__global__ void gather_k(const float* __restrict__ y, float* __restrict__ out) {
    int n = blockIdx.x;
    int c = threadIdx.x * 4;
    const float* base = y + (size_t)n * TOPK * HH + c;
    float4 a = *(float4*)(out + (size_t)n * HH + c);
    #pragma unroll
    for (int kk = 0; kk < TOPK; kk++) {
        float4 yv = *(const float4*)(base + (size_t)kk * HH);
        a.x += yv.x; a.y += yv.y; a.z += yv.z; a.w += yv.w;
    }
    *(float4*)(out + (size_t)n * HH + c) = a;
}

// ---------------- launch ----------------
extern "C" void kernel_launch(void* const* d_in, const int* in_sizes, int n_in,
                              void* d_out, int out_size) {
    const float* x    = (const float*)d_in[0];
    const float* cosp = (const float*)d_in[1];
    const float* sinp = (const float*)d_in[2];
    const float* ln1w = (const float*)d_in[3];
    const float* ln2w = (const float*)d_in[4];
    const float* Wq   = (const float*)d_in[5];
    const float* Wk   = (const float*)d_in[6];
    const float* Wv   = (const float*)d_in[7];
    const float* Wo   = (const float*)d_in[8];
    const float* Wr   = (const float*)d_in[9];
    const float* Wg   = (const float*)d_in[10];
    const float* Wu   = (const float*)d_in[11];
    const float* Wd   = (const float*)d_in[12];

    float* out    = (float*)d_out;                       // [NTOK, HH]
    float* logits = (float*)d_out + (size_t)NTOK * HH;   // [NTOK, NE]

    float *hb, *qb, *kb, *vb, *ab, *fb, *yb;
    cudaGetSymbolAddress((void**)&hb, g_h);
    cudaGetSymbolAddress((void**)&qb, g_q);
    cudaGetSymbolAddress((void**)&kb, g_k);
    cudaGetSymbolAddress((void**)&vb, g_v);
    cudaGetSymbolAddress((void**)&ab, g_att);
    cudaGetSymbolAddress((void**)&fb, g_f);
    cudaGetSymbolAddress((void**)&yb, g_y);

    int moe_smem = MOE_SMEM_FLOATS * 4;
    cudaFuncSetAttribute(moe_mma_k, cudaFuncAttributeMaxDynamicSharedMemorySize, moe_smem);
    cudaFuncSetAttribute(attn_mma_k, cudaFuncAttributeMaxDynamicSharedMemorySize, ATT_SMEM);

    // 1. rmsnorm1
    rmsnorm_k<<<NTOK, 256>>>(x, ln1w, hb);
    // 2. fused QKV (tf32 mma)
    qkv_mma_k<<<dim3(12, NTOK / 128), 256>>>(hb, Wq, Wk, Wv, qb, kb, vb);
    // 3. RoPE
    {
        int tq = NTOK * NHD * 32;
        rope_k<<<(tq + 255) / 256, 256>>>(qb, cosp, sinp, NHD, tq);
        int tkn = NTOK * NKVH * 32;
        rope_k<<<(tkn + 255) / 256, 256>>>(kb, cosp, sinp, NKVH, tkn);
    }
    // 4. attention (tf32 mma flash)
    attn_mma_k<<<dim3(TT / 128, BB * NHD), 256, ATT_SMEM>>>(qb, kb, vb, ab);
    // 5. Wo + residual -> out
    wo_mma_k<<<dim3(HH / 128, NTOK / 128), 256>>>(ab, Wo, x, out);
    // 6. rmsnorm2
    rmsnorm_k<<<NTOK, 256>>>(out, ln2w, fb);
    // 7. router logits (fp32)
    sgemm_k<<<dim3(1, NTOK / 64), 256>>>(fb, Wr, logits, NTOK, NE, HH);
    // 8-9. top-8 + scatter
    zero_cnt_k<<<1, 64>>>();
    topk_k<<<(NTOK + 255) / 256, 256>>>(logits);
    // 10. MoE (tf32 mma, fused) -> per-slot scratch
    moe_mma_k<<<dim3(NTOK / MT, NE), 256, moe_smem>>>(fb, Wg, Wu, Wd, yb);
    // 11. gather slots into out
    gather_k<<<NTOK, 256>>>(yb, out);
}

// round 15
// speedup vs baseline: 1.4670x; 1.1152x over previous
#include <cuda_runtime.h>
#include <math.h>
#include <stdint.h>

#define BB   2
#define TT   1024
#define HH   1024
#define NHD  16
#define NKVH 4
#define HDD  64
#define NE   64
#define TOPK 8
#define NI   512
#define NTOK (BB*TT)   // 2048
#define MT   64        // MoE token tile

typedef unsigned long long ull;

// ---------------- f32x2 helpers ----------------
__device__ __forceinline__ ull pk2(float a, float b) {
    ull r; asm("mov.b64 %0,{%1,%2};" : "=l"(r) : "f"(a), "f"(b)); return r;
}
__device__ __forceinline__ void fma2(ull& d, ull a, ull b) {
    asm("fma.rn.f32x2 %0,%1,%2,%0;" : "+l"(d) : "l"(a), "l"(b));
}
__device__ __forceinline__ float2 up2(ull v) {
    float2 f; asm("mov.b64 {%0,%1},%2;" : "=f"(f.x), "=f"(f.y) : "l"(v)); return f;
}

// ---------------- tf32 mma helpers ----------------
__device__ __forceinline__ void mma_tf32(float* d, const uint32_t* a, const uint32_t* b) {
    asm volatile(
        "mma.sync.aligned.m16n8k8.row.col.f32.tf32.tf32.f32 "
        "{%0,%1,%2,%3}, {%4,%5,%6,%7}, {%8,%9}, {%0,%1,%2,%3};"
        : "+f"(d[0]), "+f"(d[1]), "+f"(d[2]), "+f"(d[3])
        : "r"(a[0]), "r"(a[1]), "r"(a[2]), "r"(a[3]), "r"(b[0]), "r"(b[1]));
}
__device__ __forceinline__ uint32_t cvta_s(const void* p) {
    return (uint32_t)__cvta_generic_to_shared(p);
}
__device__ __forceinline__ void cp16(uint32_t s, const void* g) {
    asm volatile("cp.async.cg.shared.global [%0], [%1], 16;" :: "r"(s), "l"(g));
}
#define CP_COMMIT asm volatile("cp.async.commit_group;")
#define CP_WAIT0  asm volatile("cp.async.wait_group 0;")
#define CP_WAIT1  asm volatile("cp.async.wait_group 1;")

// ---------------- scratch (device globals) ----------
__device__ float g_h  [NTOK*HH];
__device__ float g_q  [NTOK*NHD*HDD];
__device__ float g_k  [NTOK*NKVH*HDD];
__device__ float g_v  [NTOK*NKVH*HDD];
__device__ float g_att[NTOK*NHD*HDD];
__device__ float g_f  [NTOK*HH];
__device__ float g_y  [(size_t)NTOK*TOPK*HH];
__device__ int   g_cnt[NE];
__device__ int   g_tok[NE*NTOK];
__device__ float g_scr[NE*NTOK];
__device__ int   g_slt[NE*NTOK];

// ---------------- rmsnorm ----------------
__global__ void rmsnorm_k(const float* __restrict__ x, const float* __restrict__ w,
                          float* __restrict__ o) {
    int row = blockIdx.x;
    const float* xr = x + (size_t)row * HH;
    float ss = 0.f;
    for (int i = threadIdx.x; i < HH; i += 256) { float v = xr[i]; ss += v * v; }
    __shared__ float red[256];
    red[threadIdx.x] = ss; __syncthreads();
    for (int s = 128; s > 0; s >>= 1) {
        if (threadIdx.x < s) red[threadIdx.x] += red[threadIdx.x + s];
        __syncthreads();
    }
    float inv = rsqrtf(red[0] * (1.0f / HH) + 1e-6f);
    float* op = o + (size_t)row * HH;
    for (int i = threadIdx.x; i < HH; i += 256) op[i] = xr[i] * inv * w[i];
}

// ======== 128x128 tf32 MMA GEMM core (QKV / Wo) ========
__device__ __forceinline__ void stageAB(int tid, int buf, int k0,
    const float* __restrict__ Ab, int K, const float* __restrict__ Bb, int N,
    float (*As)[128][20], float (*Bs)[16][136]) {
    #pragma unroll
    for (int i = 0; i < 2; i++) {
        int slot = tid + i * 256;
        int row = slot >> 2, seg = slot & 3;
        cp16(cvta_s(&As[buf][row][seg * 4]), Ab + (size_t)row * K + k0 + seg * 4);
    }
    #pragma unroll
    for (int i = 0; i < 2; i++) {
        int slot = tid + i * 256;
        int r = slot >> 5, c4 = (slot & 31) * 4;
        cp16(cvta_s(&Bs[buf][r][c4]), Bb + (size_t)(k0 + r) * N + c4);
    }
}

__device__ __forceinline__ void gemm128_mma(
    const float* __restrict__ Ab, int K, const float* __restrict__ Bb, int N,
    float (*As)[128][20], float (*Bs)[16][136],
    float acc[2][8][4], int tid)
{
    int lane = tid & 31, wid = tid >> 5;
    int wm = (wid & 3) * 32, wn = (wid >> 2) * 64;

    stageAB(tid, 0, 0, Ab, K, Bb, N, As, Bs);
    CP_COMMIT;
    int nit = K >> 4;
    for (int it = 0; it < nit; it++) {
        if (it + 1 < nit) {
            stageAB(tid, (it + 1) & 1, (it + 1) << 4, Ab, K, Bb, N, As, Bs);
            CP_COMMIT; CP_WAIT1;
        } else { CP_WAIT0; }
        __syncthreads();
        const float (*A1)[20]  = As[it & 1];
        const float (*B1)[136] = Bs[it & 1];
        #pragma unroll
        for (int k8 = 0; k8 < 16; k8 += 8) {
            int kk = k8 + (lane & 3);
            uint32_t af[2][4];
            #pragma unroll
            for (int t = 0; t < 2; t++) {
                int r = wm + t * 16 + (lane >> 2);
                af[t][0] = __float_as_uint(A1[r][kk]);
                af[t][1] = __float_as_uint(A1[r + 8][kk]);
                af[t][2] = __float_as_uint(A1[r][kk + 4]);
                af[t][3] = __float_as_uint(A1[r + 8][kk + 4]);
            }
            #pragma unroll
            for (int j = 0; j < 8; j++) {
                int c = wn + j * 8 + (lane >> 2);
                uint32_t bf[2];
                bf[0] = __float_as_uint(B1[kk][c]);
                bf[1] = __float_as_uint(B1[kk + 4][c]);
                mma_tf32(acc[0][j], af[0], bf);
                mma_tf32(acc[1][j], af[1], bf);
            }
        }
        __syncthreads();
    }
}

// ---------------- fused QKV (tf32 mma) ----------------
__global__ __launch_bounds__(256)
void qkv_mma_k(const float* __restrict__ A,
               const float* __restrict__ Wq, const float* __restrict__ Wk,
               const float* __restrict__ Wv,
               float* __restrict__ qo, float* __restrict__ ko, float* __restrict__ vo) {
    __shared__ float As[2][128][20];
    __shared__ float Bs[2][16][136];
    int bx = blockIdx.x;
    const float* Bp; float* O; int N, colb;
    if (bx < 8)       { Bp = Wq; O = qo; N = 1024; colb = bx * 128; }
    else if (bx < 10) { Bp = Wk; O = ko; N = 256;  colb = (bx - 8)  * 128; }
    else              { Bp = Wv; O = vo; N = 256;  colb = (bx - 10) * 128; }

    int tid = threadIdx.x, lane = tid & 31, wid = tid >> 5;
    int wm = (wid & 3) * 32, wn = (wid >> 2) * 64;
    int mbase = blockIdx.y * 128;
    float acc[2][8][4];
    #pragma unroll
    for (int t = 0; t < 2; t++)
        #pragma unroll
        for (int j = 0; j < 8; j++)
            #pragma unroll
            for (int q = 0; q < 4; q++) acc[t][j][q] = 0.f;

    gemm128_mma(A + (size_t)mbase * HH, HH, Bp + colb, N, As, Bs, acc, tid);

    #pragma unroll
    for (int t = 0; t < 2; t++) {
        int r0 = mbase + wm + t * 16 + (lane >> 2);
        #pragma unroll
        for (int j = 0; j < 8; j++) {
            int c = colb + wn + j * 8 + 2 * (lane & 3);
            *(float2*)(O + (size_t)r0 * N + c)       = make_float2(acc[t][j][0], acc[t][j][1]);
            *(float2*)(O + (size_t)(r0 + 8) * N + c) = make_float2(acc[t][j][2], acc[t][j][3]);
        }
    }
}

// ---------------- Wo GEMM + residual (tf32 mma) ----------------
__global__ __launch_bounds__(256)
void wo_mma_k(const float* __restrict__ A, const float* __restrict__ B,
              const float* __restrict__ R, float* __restrict__ C) {
    __shared__ float As[2][128][20];
    __shared__ float Bs[2][16][136];
    int tid = threadIdx.x, lane = tid & 31, wid = tid >> 5;
    int wm = (wid & 3) * 32, wn = (wid >> 2) * 64;
    int mbase = blockIdx.y * 128, nbase = blockIdx.x * 128;
    float acc[2][8][4];
    #pragma unroll
    for (int t = 0; t < 2; t++)
        #pragma unroll
        for (int j = 0; j < 8; j++)
            #pragma unroll
            for (int q = 0; q < 4; q++) acc[t][j][q] = 0.f;

    gemm128_mma(A + (size_t)mbase * HH, HH, B + nbase, HH, As, Bs, acc, tid);

    #pragma unroll
    for (int t = 0; t < 2; t++) {
        int r0 = mbase + wm + t * 16 + (lane >> 2);
        #pragma unroll
        for (int j = 0; j < 8; j++) {
            int c = nbase + wn + j * 8 + 2 * (lane & 3);
            float2 x0 = *(const float2*)(R + (size_t)r0 * HH + c);
            float2 x1 = *(const float2*)(R + (size_t)(r0 + 8) * HH + c);
            *(float2*)(C + (size_t)r0 * HH + c) =
                make_float2(acc[t][j][0] + x0.x, acc[t][j][1] + x0.y);
            *(float2*)(C + (size_t)(r0 + 8) * HH + c) =
                make_float2(acc[t][j][2] + x1.x, acc[t][j][3] + x1.y);
        }
    }
}

// ---------------- RoPE (in-place) ----------------
__global__ void rope_k(float* __restrict__ q, const float* __restrict__ cosp,
                       const float* __restrict__ sinp, int heads, int total) {
    int idx = blockIdx.x * blockDim.x + threadIdx.x;
    if (idx >= total) return;
    int d  = idx & 31;
    int t2 = idx >> 5;
    int hh = t2 % heads;
    int n  = t2 / heads;
    int t  = n & (TT - 1);
    float* p = q + ((size_t)n * heads + hh) * HDD;
    float c1 = cosp[t * HDD + d],      s1 = sinp[t * HDD + d];
    float c2 = cosp[t * HDD + d + 32], s2 = sinp[t * HDD + d + 32];
    float a = p[d], b = p[d + 32];
    p[d]      = a * c1 - b * s1;
    p[d + 32] = b * c2 + a * s2;
}

// ======== flash attention, tf32 mma ========
#define ATT_SMEM ((17664 + 8704) * 4)

__global__ __launch_bounds__(256, 1)
void attn_mma_k(const float* __restrict__ q, const float* __restrict__ k,
                const float* __restrict__ v, float* __restrict__ o) {
    extern __shared__ float sm[];
    float (*Qs)[68] = (float(*)[68])sm;
    float (*Ks)[68] = (float(*)[68])(sm + 8704);
    float (*Vs)[72] = (float(*)[72])(sm + 13056);
    float (*Ps)[68] = (float(*)[68])(sm + 17664);   // [8*16][68]

    int bh = blockIdx.y;
    int b = bh >> 4, h = bh & 15, kvh = h >> 2;
    int bx = blockIdx.x;
    int tid = threadIdx.x, lane = tid & 31, wq = tid >> 5;
    int gid = lane >> 2, tig = lane & 3;

    for (int i = tid; i < 128 * 16; i += 256) {
        int r = i >> 4, d4 = (i & 15) * 4;
        float4 val = *(const float4*)(q + (((size_t)(b * TT + bx * 128 + r)) * NHD + h) * HDD + d4);
        val.x *= 0.125f; val.y *= 0.125f; val.z *= 0.125f; val.w *= 0.125f;
        *(float4*)&Qs[r][d4] = val;
    }

    float o_acc[8][4];
    #pragma unroll
    for (int j = 0; j < 8; j++)
        #pragma unroll
        for (int qq = 0; qq < 4; qq++) o_acc[j][qq] = 0.f;
    float m0 = -1e30f, m1 = -1e30f, l0 = 0.f, l1 = 0.f;

    int r0g = bx * 128 + wq * 16 + gid;
    int r1g = r0g + 8;
    float (*Psw)[68] = Ps + wq * 16;

    int kv_end = (bx + 1) * 128;
    for (int j0 = 0; j0 < kv_end; j0 += 64) {
        __syncthreads();
        for (int i = tid; i < 64 * 16; i += 256) {
            int r = i >> 4, d4 = (i & 15) * 4;
            size_t base = (((size_t)(b * TT + j0 + r)) * NKVH + kvh) * HDD + d4;
            *(float4*)&Ks[r][d4] = *(const float4*)(k + base);
            *(float4*)&Vs[r][d4] = *(const float4*)(v + base);
        }
        __syncthreads();

        float s[8][4];
        #pragma unroll
        for (int j = 0; j < 8; j++)
            #pragma unroll
            for (int qq = 0; qq < 4; qq++) s[j][qq] = 0.f;
        #pragma unroll
        for (int k8 = 0; k8 < 64; k8 += 8) {
            int kk = k8 + tig;
            uint32_t af[4];
            int r = wq * 16 + gid;
            af[0] = __float_as_uint(Qs[r][kk]);
            af[1] = __float_as_uint(Qs[r + 8][kk]);
            af[2] = __float_as_uint(Qs[r][kk + 4]);
            af[3] = __float_as_uint(Qs[r + 8][kk + 4]);
            #pragma unroll
            for (int j = 0; j < 8; j++) {
                int n = j * 8 + gid;
                uint32_t bf[2];
                bf[0] = __float_as_uint(Ks[n][kk]);
                bf[1] = __float_as_uint(Ks[n][kk + 4]);
                mma_tf32(s[j], af, bf);
            }
        }

        if (j0 + 63 > r0g) {
            #pragma unroll
            for (int j = 0; j < 8; j++) {
                int cg = j0 + j * 8 + 2 * tig;
                if (cg > r0g)     s[j][0] = -1e30f;
                if (cg + 1 > r0g) s[j][1] = -1e30f;
            }
        }
        if (j0 + 63 > r1g) {
            #pragma unroll
            for (int j = 0; j < 8; j++) {
                int cg = j0 + j * 8 + 2 * tig;
                if (cg > r1g)     s[j][2] = -1e30f;
                if (cg + 1 > r1g) s[j][3] = -1e30f;
            }
        }

        float rm0 = -1e30f, rm1 = -1e30f;
        #pragma unroll
        for (int j = 0; j < 8; j++) {
            rm0 = fmaxf(rm0, fmaxf(s[j][0], s[j][1]));
            rm1 = fmaxf(rm1, fmaxf(s[j][2], s[j][3]));
        }
        #pragma unroll
        for (int off = 1; off <= 2; off <<= 1) {
            rm0 = fmaxf(rm0, __shfl_xor_sync(0xffffffff, rm0, off));
            rm1 = fmaxf(rm1, __shfl_xor_sync(0xffffffff, rm1, off));
        }
        float mn0 = fmaxf(m0, rm0), mn1 = fmaxf(m1, rm1);
        float sc0 = __expf(m0 - mn0), sc1 = __expf(m1 - mn1);
        m0 = mn0; m1 = mn1;

        float rs0 = 0.f, rs1 = 0.f;
        float p[8][4];
        #pragma unroll
        for (int j = 0; j < 8; j++) {
            p[j][0] = __expf(s[j][0] - mn0);
            p[j][1] = __expf(s[j][1] - mn0);
            p[j][2] = __expf(s[j][2] - mn1);
            p[j][3] = __expf(s[j][3] - mn1);
            rs0 += p[j][0] + p[j][1];
            rs1 += p[j][2] + p[j][3];
        }
        #pragma unroll
        for (int off = 1; off <= 2; off <<= 1) {
            rs0 += __shfl_xor_sync(0xffffffff, rs0, off);
            rs1 += __shfl_xor_sync(0xffffffff, rs1, off);
        }
        l0 = l0 * sc0 + rs0;
        l1 = l1 * sc1 + rs1;

        #pragma unroll
        for (int j = 0; j < 8; j++) {
            o_acc[j][0] *= sc0; o_acc[j][1] *= sc0;
            o_acc[j][2] *= sc1; o_acc[j][3] *= sc1;
        }

        #pragma unroll
        for (int j = 0; j < 8; j++) {
            int c = j * 8 + 2 * tig;
            Psw[gid][c]         = p[j][0];
            Psw[gid][c + 1]     = p[j][1];
            Psw[gid + 8][c]     = p[j][2];
            Psw[gid + 8][c + 1] = p[j][3];
        }
        __syncwarp();

        #pragma unroll
        for (int k8 = 0; k8 < 64; k8 += 8) {
            int kk = k8 + tig;
            uint32_t af[4];
            af[0] = __float_as_uint(Psw[gid][kk]);
            af[1] = __float_as_uint(Psw[gid + 8][kk]);
            af[2] = __float_as_uint(Psw[gid][kk + 4]);
            af[3] = __float_as_uint(Psw[gid + 8][kk + 4]);
            #pragma unroll
            for (int j = 0; j < 8; j++) {
                int n = j * 8 + gid;
                uint32_t bf[2];
                bf[0] = __float_as_uint(Vs[kk][n]);
                bf[1] = __float_as_uint(Vs[kk + 4][n]);
                mma_tf32(o_acc[j], af, bf);
            }
        }
    }

    float i0 = 1.f / l0, i1 = 1.f / l1;
    #pragma unroll
    for (int j = 0; j < 8; j++) {
        int c = j * 8 + 2 * tig;
        *(float2*)(o + (((size_t)(b * TT + r0g)) * NHD + h) * HDD + c) =
            make_float2(o_acc[j][0] * i0, o_acc[j][1] * i0);
        *(float2*)(o + (((size_t)(b * TT + r1g)) * NHD + h) * HDD + c) =
            make_float2(o_acc[j][2] * i1, o_acc[j][3] * i1);
    }
}

// ---------------- router SGEMM (fp32, N=64) ----------------
__global__ __launch_bounds__(256)
void sgemm_k(const float* __restrict__ A, const float* __restrict__ B,
             float* __restrict__ C, int M, int N, int K) {
    __shared__ ull   As2[16][64];
    __shared__ float Bs[16][64];
    int tid = threadIdx.x;
    int tx = tid & 15, ty = tid >> 4;
    const float* Ab = A + (size_t)blockIdx.y * 64 * K;
    const float* Bb = B + (size_t)blockIdx.x * 64;
    ull acc[4][2];
    #pragma unroll
    for (int i = 0; i < 4; i++) { acc[i][0] = 0ull; acc[i][1] = 0ull; }

    for (int k0 = 0; k0 < K; k0 += 16) {
        #pragma unroll
        for (int l = 0; l < 4; l++) {
            int idx = tid + l * 256;
            int m = idx >> 4, kk = idx & 15;
            float vv = Ab[(size_t)m * K + k0 + kk];
            As2[kk][m] = pk2(vv, vv);
        }
        #pragma unroll
        for (int l = 0; l < 4; l++) {
            int idx = tid + l * 256;
            int kk = idx >> 6, n = idx & 63;
            Bs[kk][n] = Bb[(size_t)(k0 + kk) * N + n];
        }
        __syncthreads();
        #pragma unroll
        for (int kk = 0; kk < 16; kk++) {
            const ull* brow = (const ull*)Bs[kk];
            ull b0 = brow[tx * 2], b1 = brow[tx * 2 + 1];
            #pragma unroll
            for (int i = 0; i < 4; i++) {
                ull a2 = As2[kk][ty * 4 + i];
                fma2(acc[i][0], a2, b0);
                fma2(acc[i][1], a2, b1);
            }
        }
        __syncthreads();
    }
    #pragma unroll
    for (int i = 0; i < 4; i++) {
        int m = blockIdx.y * 64 + ty * 4 + i;
        int nb = blockIdx.x * 64 + tx * 4;
        float2 c0 = up2(acc[i][0]), c1 = up2(acc[i][1]);
        *(float4*)(C + (size_t)m * N + nb) = make_float4(c0.x, c0.y, c1.x, c1.y);
    }
}

// ---------------- router top-8 select + expert scatter ----------------
__global__ void zero_cnt_k() {
    if (threadIdx.x < NE) g_cnt[threadIdx.x] = 0;
}

__global__ void topk_k(const float* __restrict__ logits) {
    int n = blockIdx.x * blockDim.x + threadIdx.x;
    if (n >= NTOK) return;
    float lg[NE];
    for (int e = 0; e < NE; e++) lg[e] = logits[(size_t)n * NE + e];
    int   ids[TOPK];
    float vals[TOPK];
    for (int kk = 0; kk < TOPK; kk++) {
        int best = 0; float bv = lg[0];
        for (int e = 1; e < NE; e++) if (lg[e] > bv) { bv = lg[e]; best = e; }
        ids[kk] = best; vals[kk] = bv; lg[best] = -1e30f;
    }
    float mx = vals[0], sum = 0.f;
    for (int kk = 0; kk < TOPK; kk++) { vals[kk] = __expf(vals[kk] - mx); sum += vals[kk]; }
    float inv = 1.f / sum;
    for (int kk = 0; kk < TOPK; kk++) {
        int e = ids[kk];
        int p = atomicAdd(&g_cnt[e], 1);
        g_tok[e * NTOK + p] = n;
        g_scr[e * NTOK + p] = vals[kk] * inv;
        g_slt[e * NTOK + p] = n * TOPK + kk;
    }
}

// ======== MoE: tf32 mma, 64-token tiles, warp tile 64m x 32n(x2 mats) ========
// dyn smem (floats):
//  Ast[2][64][20]  @0      (2560)
//  Gs [64][516]    @2560   (33024)
//  Wt [2][8448]    @35584  (16896)  p1: bg[16][264]+bu[16][264]; p2: bd[16][520]
//  toks/scs/slts   @52480  (192)
#define MOE_SMEM ((52480 + 192) * 4)

__global__ __launch_bounds__(256, 1)
void moe_mma_k(const float* __restrict__ f, const float* __restrict__ Wg,
               const float* __restrict__ Wu, const float* __restrict__ Wd,
               float* __restrict__ y) {
    extern __shared__ float sm[];
    float (*Ast)[64][20] = (float(*)[64][20])sm;
    float (*Gs)[516]     = (float(*)[516])(sm + 2560);
    float* Wt            = sm + 35584;
    int*   toks = (int*)(sm + 52480);
    float* scs  = (float*)(sm + 52544);
    int*   slts = (int*)(sm + 52608);

    int e  = blockIdx.y;
    int nt = g_cnt[e];
    int t0 = blockIdx.x * MT;
    if (t0 >= nt) return;

    int tid = threadIdx.x, lane = tid & 31, wid = tid >> 5;
    int gid = lane >> 2, tig = lane & 3;
    if (tid < MT) {
        int ti = t0 + tid;
        toks[tid] = (ti < nt) ? g_tok[e * NTOK + ti] : 0;
        scs[tid]  = (ti < nt) ? g_scr[e * NTOK + ti] : 0.f;
        slts[tid] = (ti < nt) ? g_slt[e * NTOK + ti] : -1;
    }
    __syncthreads();

    const float* Wge = Wg + (size_t)e * HH * NI;
    const float* Wue = Wu + (size_t)e * HH * NI;
    const float* Wde = Wd + (size_t)e * NI * HH;

    // ---------- phase 1: gate + up, two n-halves of 256 ----------
    #define P1STAGE(buf, k0, nb) do {                                          \
        {   int row = tid >> 2, seg = tid & 3;                                 \
            cp16(cvta_s(&Ast[buf][row][seg * 4]),                              \
                 f + (size_t)toks[row] * HH + (k0) + seg * 4); }               \
        float* bg = Wt + (buf) * 8448;                                         \
        float* bu = bg + 4224;                                                 \
        _Pragma("unroll")                                                      \
        for (int i = 0; i < 4; i++) {                                          \
            int slot = tid + i * 256;                                          \
            int r = slot >> 6, c4 = (slot & 63) * 4;                           \
            cp16(cvta_s(bg + r * 264 + c4), Wge + (size_t)((k0) + r) * NI + (nb) + c4); \
            cp16(cvta_s(bu + r * 264 + c4), Wue + (size_t)((k0) + r) * NI + (nb) + c4); \
        }                                                                      \
    } while (0)

    #pragma unroll 1
    for (int half = 0; half < 2; half++) {
        int nb = half * 256;
        float ag[4][4][4], au[4][4][4];
        #pragma unroll
        for (int t = 0; t < 4; t++)
            #pragma unroll
            for (int j = 0; j < 4; j++)
                #pragma unroll
                for (int q = 0; q < 4; q++) { ag[t][j][q] = 0.f; au[t][j][q] = 0.f; }

        P1STAGE(0, 0, nb); CP_COMMIT;
        for (int it = 0; it < 64; it++) {
            if (it + 1 < 64) { P1STAGE((it + 1) & 1, (it + 1) << 4, nb); CP_COMMIT; CP_WAIT1; }
            else { CP_WAIT0; }
            __syncthreads();
            const float (*A1)[20] = Ast[it & 1];
            const float* bg = Wt + (it & 1) * 8448;
            const float* bu = bg + 4224;
            #pragma unroll
            for (int k8 = 0; k8 < 16; k8 += 8) {
                int kk = k8 + tig;
                uint32_t af[4][4];
                #pragma unroll
                for (int t = 0; t < 4; t++) {
                    int r = t * 16 + gid;
                    af[t][0] = __float_as_uint(A1[r][kk]);
                    af[t][1] = __float_as_uint(A1[r + 8][kk]);
                    af[t][2] = __float_as_uint(A1[r][kk + 4]);
                    af[t][3] = __float_as_uint(A1[r + 8][kk + 4]);
                }
                #pragma unroll
                for (int j = 0; j < 4; j++) {
                    int c = wid * 32 + j * 8 + gid;
                    uint32_t bfg[2], bfu[2];
                    bfg[0] = __float_as_uint(bg[kk * 264 + c]);
                    bfg[1] = __float_as_uint(bg[(kk + 4) * 264 + c]);
                    bfu[0] = __float_as_uint(bu[kk * 264 + c]);
                    bfu[1] = __float_as_uint(bu[(kk + 4) * 264 + c]);
                    #pragma unroll
                    for (int t = 0; t < 4; t++) {
                        mma_tf32(ag[t][j], af[t], bfg);
                        mma_tf32(au[t][j], af[t], bfu);
                    }
                }
            }
            __syncthreads();
        }

        // silu(g)*u -> Gs[:, nb..nb+256)
        #pragma unroll
        for (int t = 0; t < 4; t++) {
            int r0 = t * 16 + gid;
            #pragma unroll
            for (int j = 0; j < 4; j++) {
                int c = nb + wid * 32 + j * 8 + 2 * tig;
                float g0 = ag[t][j][0], g1 = ag[t][j][1];
                float g2 = ag[t][j][2], g3 = ag[t][j][3];
                Gs[r0][c]         = g0 / (1.f + __expf(-g0)) * au[t][j][0];
                Gs[r0][c + 1]     = g1 / (1.f + __expf(-g1)) * au[t][j][1];
                Gs[r0 + 8][c]     = g2 / (1.f + __expf(-g2)) * au[t][j][2];
                Gs[r0 + 8][c + 1] = g3 / (1.f + __expf(-g3)) * au[t][j][3];
            }
        }
    }
    __syncthreads();   // Gs complete & visible

    // ---------- phase 2: down, two out-halves of 512; A read from Gs ----------
    #define P2STAGE(buf, k0, ob) do {                                          \
        float* bd = Wt + (buf) * 8448;                                         \
        _Pragma("unroll")                                                      \
        for (int i = 0; i < 8; i++) {                                          \
            int slot = tid + i * 256;                                          \
            int r = slot >> 7, c4 = (slot & 127) * 4;                          \
            cp16(cvta_s(bd + r * 520 + c4), Wde + (size_t)((k0) + r) * HH + (ob) + c4); \
        }                                                                      \
    } while (0)

    #pragma unroll 1
    for (int hp = 0; hp < 2; hp++) {
        int ob = hp * 512;
        float acc[4][8][4];
        #pragma unroll
        for (int t = 0; t < 4; t++)
            #pragma unroll
            for (int j = 0; j < 8; j++)
                #pragma unroll
                for (int q = 0; q < 4; q++) acc[t][j][q] = 0.f;

        P2STAGE(0, 0, ob); CP_COMMIT;
        for (int it = 0; it < 32; it++) {
            if (it + 1 < 32) { P2STAGE((it + 1) & 1, (it + 1) << 4, ob); CP_COMMIT; CP_WAIT1; }
            else { CP_WAIT0; }
            __syncthreads();
            const float* bd = Wt + (it & 1) * 8448;
            int k0 = it << 4;
            #pragma unroll
            for (int k8 = 0; k8 < 16; k8 += 8) {
                int kk = k0 + k8 + tig;
                uint32_t af[4][4];
                #pragma unroll
                for (int t = 0; t < 4; t++) {
                    int r = t * 16 + gid;
                    af[t][0] = __float_as_uint(Gs[r][kk]);
                    af[t][1] = __float_as_uint(Gs[r + 8][kk]);
                    af[t][2] = __float_as_uint(Gs[r][kk + 4]);
                    af[t][3] = __float_as_uint(Gs[r + 8][kk + 4]);
                }
                int kl = k8 + tig;
                #pragma unroll
                for (int j = 0; j < 8; j++) {
                    int c = wid * 64 + j * 8 + gid;
                    uint32_t bf[2];
                    bf[0] = __float_as_uint(bd[kl * 520 + c]);
                    bf[1] = __float_as_uint(bd[(kl + 4) * 520 + c]);
                    #pragma unroll
                    for (int t = 0; t < 4; t++) mma_tf32(acc[t][j], af[t], bf);
                }
            }
            __syncthreads();
        }

        // epilogue: scale & write y slots for this out-half
        #pragma unroll
        for (int t = 0; t < 4; t++) {
            int r0 = t * 16 + gid;
            int s0 = slts[r0], s1 = slts[r0 + 8];
            float c0 = scs[r0], c1 = scs[r0 + 8];
            #pragma unroll
            for (int j = 0; j < 8; j++) {
                int c = ob + wid * 64 + j * 8 + 2 * tig;
                if (s0 >= 0)
                    *(float2*)(y + (size_t)s0 * HH + c) =
                        make_float2(c0 * acc[t][j][0], c0 * acc[t][j][1]);
                if (s1 >= 0)
                    *(float2*)(y + (size_t)s1 * HH + c) =
                        make_float2(c1 * acc[t][j][2], c1 * acc[t][j][3]);
            }
        }
    }
    #undef P1STAGE
    #undef P2STAGE
}

// ---------------- gather: out += sum_k y[(n,k)] ----------------
__global__ void gather_k(const float* __restrict__ y, float* __restrict__ out) {
    int n = blockIdx.x;
    int c = threadIdx.x * 4;
    const float* base = y + (size_t)n * TOPK * HH + c;
    float4 a = *(float4*)(out + (size_t)n * HH + c);
    #pragma unroll
    for (int kk = 0; kk < TOPK; kk++) {
        float4 yv = *(const float4*)(base + (size_t)kk * HH);
        a.x += yv.x; a.y += yv.y; a.z += yv.z; a.w += yv.w;
    }
    *(float4*)(out + (size_t)n * HH + c) = a;
}

// ---------------- launch ----------------
extern "C" void kernel_launch(void* const* d_in, const int* in_sizes, int n_in,
                              void* d_out, int out_size) {
    const float* x    = (const float*)d_in[0];
    const float* cosp = (const float*)d_in[1];
    const float* sinp = (const float*)d_in[2];
    const float* ln1w = (const float*)d_in[3];
    const float* ln2w = (const float*)d_in[4];
    const float* Wq   = (const float*)d_in[5];
    const float* Wk   = (const float*)d_in[6];
    const float* Wv   = (const float*)d_in[7];
    const float* Wo   = (const float*)d_in[8];
    const float* Wr   = (const float*)d_in[9];
    const float* Wg   = (const float*)d_in[10];
    const float* Wu   = (const float*)d_in[11];
    const float* Wd   = (const float*)d_in[12];

    float* out    = (float*)d_out;                       // [NTOK, HH]
    float* logits = (float*)d_out + (size_t)NTOK * HH;   // [NTOK, NE]

    float *hb, *qb, *kb, *vb, *ab, *fb, *yb;
    cudaGetSymbolAddress((void**)&hb, g_h);
    cudaGetSymbolAddress((void**)&qb, g_q);
    cudaGetSymbolAddress((void**)&kb, g_k);
    cudaGetSymbolAddress((void**)&vb, g_v);
    cudaGetSymbolAddress((void**)&ab, g_att);
    cudaGetSymbolAddress((void**)&fb, g_f);
    cudaGetSymbolAddress((void**)&yb, g_y);

    cudaFuncSetAttribute(moe_mma_k, cudaFuncAttributeMaxDynamicSharedMemorySize, MOE_SMEM);
    cudaFuncSetAttribute(attn_mma_k, cudaFuncAttributeMaxDynamicSharedMemorySize, ATT_SMEM);

    // 1. rmsnorm1
    rmsnorm_k<<<NTOK, 256>>>(x, ln1w, hb);
    // 2. fused QKV (tf32 mma)
    qkv_mma_k<<<dim3(12, NTOK / 128), 256>>>(hb, Wq, Wk, Wv, qb, kb, vb);
    // 3. RoPE
    {
        int tq = NTOK * NHD * 32;
        rope_k<<<(tq + 255) / 256, 256>>>(qb, cosp, sinp, NHD, tq);
        int tkn = NTOK * NKVH * 32;
        rope_k<<<(tkn + 255) / 256, 256>>>(kb, cosp, sinp, NKVH, tkn);
    }
    // 4. attention (tf32 mma flash)
    attn_mma_k<<<dim3(TT / 128, BB * NHD), 256, ATT_SMEM>>>(qb, kb, vb, ab);
    // 5. Wo + residual -> out
    wo_mma_k<<<dim3(HH / 128, NTOK / 128), 256>>>(ab, Wo, x, out);
    // 6. rmsnorm2
    rmsnorm_k<<<NTOK, 256>>>(out, ln2w, fb);
    // 7. router logits (fp32)
    sgemm_k<<<dim3(1, NTOK / 64), 256>>>(fb, Wr, logits, NTOK, NE, HH);
    // 8-9. top-8 + scatter
    zero_cnt_k<<<1, 64>>>();
    topk_k<<<(NTOK + 255) / 256, 256>>>(logits);
    // 10. MoE (tf32 mma, 64-token tiles) -> per-slot scratch
    moe_mma_k<<<dim3(NTOK / MT, NE), 256, MOE_SMEM>>>(fb, Wg, Wu, Wd, yb);
    // 11. gather slots into out
    gather_k<<<NTOK, 256>>>(yb, out);
}

// round 16
// speedup vs baseline: 1.5764x; 1.0746x over previous
#include <cuda_runtime.h>
#include <cuda_fp16.h>
#include <math.h>
#include <stdint.h>

#define BB   2
#define TT   1024
#define HH   1024
#define NHD  16
#define NKVH 4
#define HDD  64
#define NE   64
#define TOPK 8
#define NI   512
#define NTOK (BB*TT)   // 2048
#define MT   64        // MoE token tile

typedef unsigned long long ull;

// ---------------- f32x2 helpers (router) ----------------
__device__ __forceinline__ ull pk2(float a, float b) {
    ull r; asm("mov.b64 %0,{%1,%2};" : "=l"(r) : "f"(a), "f"(b)); return r;
}
__device__ __forceinline__ void fma2(ull& d, ull a, ull b) {
    asm("fma.rn.f32x2 %0,%1,%2,%0;" : "+l"(d) : "l"(a), "l"(b));
}
__device__ __forceinline__ float2 up2(ull v) {
    float2 f; asm("mov.b64 {%0,%1},%2;" : "=f"(f.x), "=f"(f.y) : "l"(v)); return f;
}

// ---------------- mma helpers ----------------
__device__ __forceinline__ void mma_tf32(float* d, const uint32_t* a, const uint32_t* b) {
    asm volatile(
        "mma.sync.aligned.m16n8k8.row.col.f32.tf32.tf32.f32 "
        "{%0,%1,%2,%3}, {%4,%5,%6,%7}, {%8,%9}, {%0,%1,%2,%3};"
        : "+f"(d[0]), "+f"(d[1]), "+f"(d[2]), "+f"(d[3])
        : "r"(a[0]), "r"(a[1]), "r"(a[2]), "r"(a[3]), "r"(b[0]), "r"(b[1]));
}
__device__ __forceinline__ void mma_f16(float* d, const uint32_t* a, const uint32_t* b) {
    asm volatile(
        "mma.sync.aligned.m16n8k16.row.col.f32.f16.f16.f32 "
        "{%0,%1,%2,%3}, {%4,%5,%6,%7}, {%8,%9}, {%0,%1,%2,%3};"
        : "+f"(d[0]), "+f"(d[1]), "+f"(d[2]), "+f"(d[3])
        : "r"(a[0]), "r"(a[1]), "r"(a[2]), "r"(a[3]), "r"(b[0]), "r"(b[1]));
}
__device__ __forceinline__ uint32_t cvta_s(const void* p) {
    return (uint32_t)__cvta_generic_to_shared(p);
}
__device__ __forceinline__ void cp16(uint32_t s, const void* g) {
    asm volatile("cp.async.cg.shared.global [%0], [%1], 16;" :: "r"(s), "l"(g));
}
#define CP_COMMIT asm volatile("cp.async.commit_group;")
#define CP_WAIT0  asm volatile("cp.async.wait_group 0;")
#define CP_WAIT1  asm volatile("cp.async.wait_group 1;")

// ---------------- scratch (device globals) ----------
__device__ float  g_q  [NTOK*NHD*HDD];
__device__ float  g_k  [NTOK*NKVH*HDD];
__device__ float  g_v  [NTOK*NKVH*HDD];
__device__ float  g_f  [NTOK*HH];
__device__ float  g_y  [(size_t)NTOK*TOPK*HH];
__device__ __half g_h16  [NTOK*HH];
__device__ __half g_f16  [NTOK*HH];
__device__ __half g_att16[NTOK*NHD*HDD];
__device__ __half g_wq16[HH*HH];            // transposed [n][k]
__device__ __half g_wk16[HH*NKVH*HDD];
__device__ __half g_wv16[HH*NKVH*HDD];
__device__ __half g_wo16[HH*HH];
__device__ __half g_wg16[(size_t)NE*NI*HH]; // [e][inter][h]
__device__ __half g_wu16[(size_t)NE*NI*HH];
__device__ __half g_wd16[(size_t)NE*HH*NI]; // [e][hout][i]
__device__ int    g_cnt[NE];
__device__ int    g_tok[NE*NTOK];
__device__ float  g_scr[NE*NTOK];
__device__ int    g_slt[NE*NTOK];

// ---------------- transpose-convert: out[c][r] = half(in[r][c]) ----------------
__global__ void tconv_k(const float* __restrict__ in, __half* __restrict__ out,
                        int R, int C) {
    __shared__ float t[32][33];
    size_t moff = (size_t)blockIdx.z * R * C;
    in += moff; out += moff;
    int c0 = blockIdx.x * 32, r0 = blockIdx.y * 32;
    #pragma unroll
    for (int i = 0; i < 4; i++) {
        int r = threadIdx.y + i * 8;
        t[r][threadIdx.x] = in[(size_t)(r0 + r) * C + c0 + threadIdx.x];
    }
    __syncthreads();
    #pragma unroll
    for (int i = 0; i < 4; i++) {
        int cc = threadIdx.y + i * 8;
        out[(size_t)(c0 + cc) * R + r0 + threadIdx.x] = __float2half(t[threadIdx.x][cc]);
    }
}

// ---------------- rmsnorm (fp32 in -> optional fp32 + half out) ----------------
__global__ void rmsnorm_k(const float* __restrict__ x, const float* __restrict__ w,
                          float* __restrict__ o, __half* __restrict__ o16) {
    int row = blockIdx.x;
    const float* xr = x + (size_t)row * HH;
    float ss = 0.f;
    for (int i = threadIdx.x; i < HH; i += 256) { float v = xr[i]; ss += v * v; }
    __shared__ float red[256];
    red[threadIdx.x] = ss; __syncthreads();
    for (int s = 128; s > 0; s >>= 1) {
        if (threadIdx.x < s) red[threadIdx.x] += red[threadIdx.x + s];
        __syncthreads();
    }
    float inv = rsqrtf(red[0] * (1.0f / HH) + 1e-6f);
    for (int i = threadIdx.x; i < HH; i += 256) {
        float v = xr[i] * inv * w[i];
        if (o) o[(size_t)row * HH + i] = v;
        o16[(size_t)row * HH + i] = __float2half(v);
    }
}

// ======== 128x128 fp16 MMA GEMM core (A [m][K], B transposed [n][K]) ========
__device__ __forceinline__ void stageABh(int tid, int buf, int k0,
    const __half* __restrict__ Ab, const __half* __restrict__ Bb, int K,
    uint32_t (*Ah)[128][20], uint32_t (*Bh)[128][20]) {
    #pragma unroll
    for (int i = 0; i < 2; i++) {
        int slot = tid + i * 256;
        int row = slot >> 2, seg = slot & 3;
        cp16(cvta_s(&Ah[buf][row][seg * 4]), Ab + (size_t)row * K + k0 + seg * 8);
    }
    #pragma unroll
    for (int i = 0; i < 2; i++) {
        int slot = tid + i * 256;
        int row = slot >> 2, seg = slot & 3;
        cp16(cvta_s(&Bh[buf][row][seg * 4]), Bb + (size_t)row * K + k0 + seg * 8);
    }
}

__device__ __forceinline__ void gemm128h(
    const __half* __restrict__ Ab, const __half* __restrict__ Bb, int K,
    uint32_t (*Ah)[128][20], uint32_t (*Bh)[128][20],
    float acc[2][8][4], int tid)
{
    int lane = tid & 31, wid = tid >> 5;
    int wm = (wid & 3) * 32, wn = (wid >> 2) * 64;
    int gid = lane >> 2, tig = lane & 3;

    stageABh(tid, 0, 0, Ab, Bb, K, Ah, Bh);
    CP_COMMIT;
    int nit = K >> 5;
    for (int it = 0; it < nit; it++) {
        if (it + 1 < nit) {
            stageABh(tid, (it + 1) & 1, (it + 1) << 5, Ab, Bb, K, Ah, Bh);
            CP_COMMIT; CP_WAIT1;
        } else { CP_WAIT0; }
        __syncthreads();
        const uint32_t (*A1)[20] = Ah[it & 1];
        const uint32_t (*B1)[20] = Bh[it & 1];
        #pragma unroll
        for (int kw = 0; kw < 16; kw += 8) {
            uint32_t af[2][4];
            #pragma unroll
            for (int t = 0; t < 2; t++) {
                int r = wm + t * 16 + gid;
                af[t][0] = A1[r][kw + tig];
                af[t][1] = A1[r + 8][kw + tig];
                af[t][2] = A1[r][kw + 4 + tig];
                af[t][3] = A1[r + 8][kw + 4 + tig];
            }
            #pragma unroll
            for (int j = 0; j < 8; j++) {
                int n = wn + j * 8 + gid;
                uint32_t bf[2];
                bf[0] = B1[n][kw + tig];
                bf[1] = B1[n][kw + 4 + tig];
                mma_f16(acc[0][j], af[0], bf);
                mma_f16(acc[1][j], af[1], bf);
            }
        }
        __syncthreads();
    }
}

// ---------------- fused QKV (fp16 mma) ----------------
__global__ __launch_bounds__(256)
void qkv_mma_k(const __half* __restrict__ A,
               const __half* __restrict__ Wq, const __half* __restrict__ Wk,
               const __half* __restrict__ Wv,
               float* __restrict__ qo, float* __restrict__ ko, float* __restrict__ vo) {
    __shared__ __align__(16) uint32_t Ah[2][128][20];
    __shared__ __align__(16) uint32_t Bh[2][128][20];
    int bx = blockIdx.x;
    const __half* Bp; float* O; int N, colb;
    if (bx < 8)       { Bp = Wq; O = qo; N = 1024; colb = bx * 128; }
    else if (bx < 10) { Bp = Wk; O = ko; N = 256;  colb = (bx - 8)  * 128; }
    else              { Bp = Wv; O = vo; N = 256;  colb = (bx - 10) * 128; }

    int tid = threadIdx.x, lane = tid & 31, wid = tid >> 5;
    int wm = (wid & 3) * 32, wn = (wid >> 2) * 64;
    int mbase = blockIdx.y * 128;
    float acc[2][8][4];
    #pragma unroll
    for (int t = 0; t < 2; t++)
        #pragma unroll
        for (int j = 0; j < 8; j++)
            #pragma unroll
            for (int q = 0; q < 4; q++) acc[t][j][q] = 0.f;

    // B transposed: rows are output cols
    gemm128h(A + (size_t)mbase * HH, Bp + (size_t)colb * HH, HH, Ah, Bh, acc, tid);

    #pragma unroll
    for (int t = 0; t < 2; t++) {
        int r0 = mbase + wm + t * 16 + (lane >> 2);
        #pragma unroll
        for (int j = 0; j < 8; j++) {
            int c = colb + wn + j * 8 + 2 * (lane & 3);
            *(float2*)(O + (size_t)r0 * N + c)       = make_float2(acc[t][j][0], acc[t][j][1]);
            *(float2*)(O + (size_t)(r0 + 8) * N + c) = make_float2(acc[t][j][2], acc[t][j][3]);
        }
    }
}

// ---------------- Wo GEMM + residual (fp16 mma) ----------------
__global__ __launch_bounds__(256)
void wo_mma_k(const __half* __restrict__ A, const __half* __restrict__ B,
              const float* __restrict__ R, float* __restrict__ C) {
    __shared__ __align__(16) uint32_t Ah[2][128][20];
    __shared__ __align__(16) uint32_t Bh[2][128][20];
    int tid = threadIdx.x, lane = tid & 31, wid = tid >> 5;
    int wm = (wid & 3) * 32, wn = (wid >> 2) * 64;
    int mbase = blockIdx.y * 128, nbase = blockIdx.x * 128;
    float acc[2][8][4];
    #pragma unroll
    for (int t = 0; t < 2; t++)
        #pragma unroll
        for (int j = 0; j < 8; j++)
            #pragma unroll
            for (int q = 0; q < 4; q++) acc[t][j][q] = 0.f;

    gemm128h(A + (size_t)mbase * HH, B + (size_t)nbase * HH, HH, Ah, Bh, acc, tid);

    #pragma unroll
    for (int t = 0; t < 2; t++) {
        int r0 = mbase + wm + t * 16 + (lane >> 2);
        #pragma unroll
        for (int j = 0; j < 8; j++) {
            int c = nbase + wn + j * 8 + 2 * (lane & 3);
            float2 x0 = *(const float2*)(R + (size_t)r0 * HH + c);
            float2 x1 = *(const float2*)(R + (size_t)(r0 + 8) * HH + c);
            *(float2*)(C + (size_t)r0 * HH + c) =
                make_float2(acc[t][j][0] + x0.x, acc[t][j][1] + x0.y);
            *(float2*)(C + (size_t)(r0 + 8) * HH + c) =
                make_float2(acc[t][j][2] + x1.x, acc[t][j][3] + x1.y);
        }
    }
}

// ---------------- RoPE (in-place) ----------------
__global__ void rope_k(float* __restrict__ q, const float* __restrict__ cosp,
                       const float* __restrict__ sinp, int heads, int total) {
    int idx = blockIdx.x * blockDim.x + threadIdx.x;
    if (idx >= total) return;
    int d  = idx & 31;
    int t2 = idx >> 5;
    int hh = t2 % heads;
    int n  = t2 / heads;
    int t  = n & (TT - 1);
    float* p = q + ((size_t)n * heads + hh) * HDD;
    float c1 = cosp[t * HDD + d],      s1 = sinp[t * HDD + d];
    float c2 = cosp[t * HDD + d + 32], s2 = sinp[t * HDD + d + 32];
    float a = p[d], b = p[d + 32];
    p[d]      = a * c1 - b * s1;
    p[d + 32] = b * c2 + a * s2;
}

// ======== flash attention, tf32 mma (output stored as half) ========
#define ATT_SMEM ((17664 + 8704) * 4)

__global__ __launch_bounds__(256, 1)
void attn_mma_k(const float* __restrict__ q, const float* __restrict__ k,
                const float* __restrict__ v, __half* __restrict__ o16) {
    extern __shared__ float sm[];
    float (*Qs)[68] = (float(*)[68])sm;
    float (*Ks)[68] = (float(*)[68])(sm + 8704);
    float (*Vs)[72] = (float(*)[72])(sm + 13056);
    float (*Ps)[68] = (float(*)[68])(sm + 17664);

    int bh = blockIdx.y;
    int b = bh >> 4, h = bh & 15, kvh = h >> 2;
    int bx = blockIdx.x;
    int tid = threadIdx.x, lane = tid & 31, wq = tid >> 5;
    int gid = lane >> 2, tig = lane & 3;

    for (int i = tid; i < 128 * 16; i += 256) {
        int r = i >> 4, d4 = (i & 15) * 4;
        float4 val = *(const float4*)(q + (((size_t)(b * TT + bx * 128 + r)) * NHD + h) * HDD + d4);
        val.x *= 0.125f; val.y *= 0.125f; val.z *= 0.125f; val.w *= 0.125f;
        *(float4*)&Qs[r][d4] = val;
    }

    float o_acc[8][4];
    #pragma unroll
    for (int j = 0; j < 8; j++)
        #pragma unroll
        for (int qq = 0; qq < 4; qq++) o_acc[j][qq] = 0.f;
    float m0 = -1e30f, m1 = -1e30f, l0 = 0.f, l1 = 0.f;

    int r0g = bx * 128 + wq * 16 + gid;
    int r1g = r0g + 8;
    float (*Psw)[68] = Ps + wq * 16;

    int kv_end = (bx + 1) * 128;
    for (int j0 = 0; j0 < kv_end; j0 += 64) {
        __syncthreads();
        for (int i = tid; i < 64 * 16; i += 256) {
            int r = i >> 4, d4 = (i & 15) * 4;
            size_t base = (((size_t)(b * TT + j0 + r)) * NKVH + kvh) * HDD + d4;
            *(float4*)&Ks[r][d4] = *(const float4*)(k + base);
            *(float4*)&Vs[r][d4] = *(const float4*)(v + base);
        }
        __syncthreads();

        float s[8][4];
        #pragma unroll
        for (int j = 0; j < 8; j++)
            #pragma unroll
            for (int qq = 0; qq < 4; qq++) s[j][qq] = 0.f;
        #pragma unroll
        for (int k8 = 0; k8 < 64; k8 += 8) {
            int kk = k8 + tig;
            uint32_t af[4];
            int r = wq * 16 + gid;
            af[0] = __float_as_uint(Qs[r][kk]);
            af[1] = __float_as_uint(Qs[r + 8][kk]);
            af[2] = __float_as_uint(Qs[r][kk + 4]);
            af[3] = __float_as_uint(Qs[r + 8][kk + 4]);
            #pragma unroll
            for (int j = 0; j < 8; j++) {
                int n = j * 8 + gid;
                uint32_t bf[2];
                bf[0] = __float_as_uint(Ks[n][kk]);
                bf[1] = __float_as_uint(Ks[n][kk + 4]);
                mma_tf32(s[j], af, bf);
            }
        }

        if (j0 + 63 > r0g) {
            #pragma unroll
            for (int j = 0; j < 8; j++) {
                int cg = j0 + j * 8 + 2 * tig;
                if (cg > r0g)     s[j][0] = -1e30f;
                if (cg + 1 > r0g) s[j][1] = -1e30f;
            }
        }
        if (j0 + 63 > r1g) {
            #pragma unroll
            for (int j = 0; j < 8; j++) {
                int cg = j0 + j * 8 + 2 * tig;
                if (cg > r1g)     s[j][2] = -1e30f;
                if (cg + 1 > r1g) s[j][3] = -1e30f;
            }
        }

        float rm0 = -1e30f, rm1 = -1e30f;
        #pragma unroll
        for (int j = 0; j < 8; j++) {
            rm0 = fmaxf(rm0, fmaxf(s[j][0], s[j][1]));
            rm1 = fmaxf(rm1, fmaxf(s[j][2], s[j][3]));
        }
        #pragma unroll
        for (int off = 1; off <= 2; off <<= 1) {
            rm0 = fmaxf(rm0, __shfl_xor_sync(0xffffffff, rm0, off));
            rm1 = fmaxf(rm1, __shfl_xor_sync(0xffffffff, rm1, off));
        }
        float mn0 = fmaxf(m0, rm0), mn1 = fmaxf(m1, rm1);
        float sc0 = __expf(m0 - mn0), sc1 = __expf(m1 - mn1);
        m0 = mn0; m1 = mn1;

        float rs0 = 0.f, rs1 = 0.f;
        float p[8][4];
        #pragma unroll
        for (int j = 0; j < 8; j++) {
            p[j][0] = __expf(s[j][0] - mn0);
            p[j][1] = __expf(s[j][1] - mn0);
            p[j][2] = __expf(s[j][2] - mn1);
            p[j][3] = __expf(s[j][3] - mn1);
            rs0 += p[j][0] + p[j][1];
            rs1 += p[j][2] + p[j][3];
        }
        #pragma unroll
        for (int off = 1; off <= 2; off <<= 1) {
            rs0 += __shfl_xor_sync(0xffffffff, rs0, off);
            rs1 += __shfl_xor_sync(0xffffffff, rs1, off);
        }
        l0 = l0 * sc0 + rs0;
        l1 = l1 * sc1 + rs1;

        #pragma unroll
        for (int j = 0; j < 8; j++) {
            o_acc[j][0] *= sc0; o_acc[j][1] *= sc0;
            o_acc[j][2] *= sc1; o_acc[j][3] *= sc1;
        }

        #pragma unroll
        for (int j = 0; j < 8; j++) {
            int c = j * 8 + 2 * tig;
            Psw[gid][c]         = p[j][0];
            Psw[gid][c + 1]     = p[j][1];
            Psw[gid + 8][c]     = p[j][2];
            Psw[gid + 8][c + 1] = p[j][3];
        }
        __syncwarp();

        #pragma unroll
        for (int k8 = 0; k8 < 64; k8 += 8) {
            int kk = k8 + tig;
            uint32_t af[4];
            af[0] = __float_as_uint(Psw[gid][kk]);
            af[1] = __float_as_uint(Psw[gid + 8][kk]);
            af[2] = __float_as_uint(Psw[gid][kk + 4]);
            af[3] = __float_as_uint(Psw[gid + 8][kk + 4]);
            #pragma unroll
            for (int j = 0; j < 8; j++) {
                int n = j * 8 + gid;
                uint32_t bf[2];
                bf[0] = __float_as_uint(Vs[kk][n]);
                bf[1] = __float_as_uint(Vs[kk + 4][n]);
                mma_tf32(o_acc[j], af, bf);
            }
        }
    }

    float i0 = 1.f / l0, i1 = 1.f / l1;
    #pragma unroll
    for (int j = 0; j < 8; j++) {
        int c = j * 8 + 2 * tig;
        *(__half2*)(o16 + (((size_t)(b * TT + r0g)) * NHD + h) * HDD + c) =
            __floats2half2_rn(o_acc[j][0] * i0, o_acc[j][1] * i0);
        *(__half2*)(o16 + (((size_t)(b * TT + r1g)) * NHD + h) * HDD + c) =
            __floats2half2_rn(o_acc[j][2] * i1, o_acc[j][3] * i1);
    }
}

// ---------------- router SGEMM (fp32, N=64) ----------------
__global__ __launch_bounds__(256)
void sgemm_k(const float* __restrict__ A, const float* __restrict__ B,
             float* __restrict__ C, int M, int N, int K) {
    __shared__ ull   As2[16][64];
    __shared__ float Bs[16][64];
    int tid = threadIdx.x;
    int tx = tid & 15, ty = tid >> 4;
    const float* Ab = A + (size_t)blockIdx.y * 64 * K;
    const float* Bb = B + (size_t)blockIdx.x * 64;
    ull acc[4][2];
    #pragma unroll
    for (int i = 0; i < 4; i++) { acc[i][0] = 0ull; acc[i][1] = 0ull; }

    for (int k0 = 0; k0 < K; k0 += 16) {
        #pragma unroll
        for (int l = 0; l < 4; l++) {
            int idx = tid + l * 256;
            int m = idx >> 4, kk = idx & 15;
            float vv = Ab[(size_t)m * K + k0 + kk];
            As2[kk][m] = pk2(vv, vv);
        }
        #pragma unroll
        for (int l = 0; l < 4; l++) {
            int idx = tid + l * 256;
            int kk = idx >> 6, n = idx & 63;
            Bs[kk][n] = Bb[(size_t)(k0 + kk) * N + n];
        }
        __syncthreads();
        #pragma unroll
        for (int kk = 0; kk < 16; kk++) {
            const ull* brow = (const ull*)Bs[kk];
            ull b0 = brow[tx * 2], b1 = brow[tx * 2 + 1];
            #pragma unroll
            for (int i = 0; i < 4; i++) {
                ull a2 = As2[kk][ty * 4 + i];
                fma2(acc[i][0], a2, b0);
                fma2(acc[i][1], a2, b1);
            }
        }
        __syncthreads();
    }
    #pragma unroll
    for (int i = 0; i < 4; i++) {
        int m = blockIdx.y * 64 + ty * 4 + i;
        int nb = blockIdx.x * 64 + tx * 4;
        float2 c0 = up2(acc[i][0]), c1 = up2(acc[i][1]);
        *(float4*)(C + (size_t)m * N + nb) = make_float4(c0.x, c0.y, c1.x, c1.y);
    }
}

// ---------------- router top-8 select + expert scatter ----------------
__global__ void zero_cnt_k() {
    if (threadIdx.x < NE) g_cnt[threadIdx.x] = 0;
}

__global__ void topk_k(const float* __restrict__ logits) {
    int n = blockIdx.x * blockDim.x + threadIdx.x;
    if (n >= NTOK) return;
    float lg[NE];
    for (int e = 0; e < NE; e++) lg[e] = logits[(size_t)n * NE + e];
    int   ids[TOPK];
    float vals[TOPK];
    for (int kk = 0; kk < TOPK; kk++) {
        int best = 0; float bv = lg[0];
        for (int e = 1; e < NE; e++) if (lg[e] > bv) { bv = lg[e]; best = e; }
        ids[kk] = best; vals[kk] = bv; lg[best] = -1e30f;
    }
    float mx = vals[0], sum = 0.f;
    for (int kk = 0; kk < TOPK; kk++) { vals[kk] = __expf(vals[kk] - mx); sum += vals[kk]; }
    float inv = 1.f / sum;
    for (int kk = 0; kk < TOPK; kk++) {
        int e = ids[kk];
        int p = atomicAdd(&g_cnt[e], 1);
        g_tok[e * NTOK + p] = n;
        g_scr[e * NTOK + p] = vals[kk] * inv;
        g_slt[e * NTOK + p] = n * TOPK + kk;
    }
}

// ======== MoE: fp16 mma, 64-token tiles ========
// word-layout (uint32 units):
//  AstW [2*64][20]  @0       (2560 w)
//  GsW  [64][260]   @2560    (16640 w)  half2 words, 512 halves/row + pad
//  WtW  [2][10240]  @19200   (20480 w)  p1: bg[256][20]+bu[256][20]; p2: bd[512][20]
//  toks @39680, scs @39744, slts @39808 ; end 39872 w
#define MOE_SMEM (39872 * 4 + 256)

__global__ __launch_bounds__(256, 1)
void moe_mma_k(const __half* __restrict__ f16, const __half* __restrict__ Wg,
               const __half* __restrict__ Wu, const __half* __restrict__ Wd,
               float* __restrict__ y) {
    extern __shared__ uint32_t smw[];
    uint32_t (*AstW)[20] = (uint32_t(*)[20])smw;
    uint32_t (*GsW)[260] = (uint32_t(*)[260])(smw + 2560);
    uint32_t* WtW        = smw + 19200;
    int*   toks = (int*)(smw + 39680);
    float* scs  = (float*)(smw + 39744);
    int*   slts = (int*)(smw + 39808);

    int e  = blockIdx.y;
    int nt = g_cnt[e];
    int t0 = blockIdx.x * MT;
    if (t0 >= nt) return;

    int tid = threadIdx.x, lane = tid & 31, wid = tid >> 5;
    int gid = lane >> 2, tig = lane & 3;
    if (tid < MT) {
        int ti = t0 + tid;
        toks[tid] = (ti < nt) ? g_tok[e * NTOK + ti] : 0;
        scs[tid]  = (ti < nt) ? g_scr[e * NTOK + ti] : 0.f;
        slts[tid] = (ti < nt) ? g_slt[e * NTOK + ti] : -1;
    }
    __syncthreads();

    const __half* wg16e = Wg + (size_t)e * NI * HH;  // [inter][h]
    const __half* wu16e = Wu + (size_t)e * NI * HH;
    const __half* wd16e = Wd + (size_t)e * HH * NI;  // [hout][i]

    // ---------- phase 1: gate+up, two n-halves of 256, K=1024 step 32 ----------
    #define P1STAGE(buf, k0, nb) do {                                              \
        {   int row = tid >> 2, seg = tid & 3;                                     \
            cp16(cvta_s(&AstW[(buf) * 64 + row][seg * 4]),                         \
                 f16 + (size_t)toks[row] * HH + (k0) + seg * 8); }                 \
        uint32_t* bg = WtW + (buf) * 10240;                                        \
        uint32_t* bu = bg + 5120;                                                  \
        _Pragma("unroll")                                                          \
        for (int i = 0; i < 4; i++) {                                              \
            int slot = tid + i * 256;                                              \
            int row = slot >> 2, seg = slot & 3;                                   \
            cp16(cvta_s(bg + row * 20 + seg * 4),                                  \
                 wg16e + (size_t)((nb) + row) * HH + (k0) + seg * 8);              \
            cp16(cvta_s(bu + row * 20 + seg * 4),                                  \
                 wu16e + (size_t)((nb) + row) * HH + (k0) + seg * 8);              \
        }                                                                          \
    } while (0)

    #pragma unroll 1
    for (int half = 0; half < 2; half++) {
        int nb = half * 256;
        float ag[4][4][4], au[4][4][4];
        #pragma unroll
        for (int t = 0; t < 4; t++)
            #pragma unroll
            for (int j = 0; j < 4; j++)
                #pragma unroll
                for (int q = 0; q < 4; q++) { ag[t][j][q] = 0.f; au[t][j][q] = 0.f; }

        P1STAGE(0, 0, nb); CP_COMMIT;
        for (int it = 0; it < 32; it++) {
            if (it + 1 < 32) { P1STAGE((it + 1) & 1, (it + 1) << 5, nb); CP_COMMIT; CP_WAIT1; }
            else { CP_WAIT0; }
            __syncthreads();
            const uint32_t (*A1)[20] = AstW + (it & 1) * 64;
            const uint32_t* bg = WtW + (it & 1) * 10240;
            const uint32_t* bu = bg + 5120;
            #pragma unroll
            for (int kw = 0; kw < 16; kw += 8) {
                uint32_t af[4][4];
                #pragma unroll
                for (int t = 0; t < 4; t++) {
                    int r = t * 16 + gid;
                    af[t][0] = A1[r][kw + tig];
                    af[t][1] = A1[r + 8][kw + tig];
                    af[t][2] = A1[r][kw + 4 + tig];
                    af[t][3] = A1[r + 8][kw + 4 + tig];
                }
                #pragma unroll
                for (int j = 0; j < 4; j++) {
                    int n = wid * 32 + j * 8 + gid;
                    uint32_t bfg[2], bfu[2];
                    bfg[0] = bg[n * 20 + kw + tig];
                    bfg[1] = bg[n * 20 + kw + 4 + tig];
                    bfu[0] = bu[n * 20 + kw + tig];
                    bfu[1] = bu[n * 20 + kw + 4 + tig];
                    #pragma unroll
                    for (int t = 0; t < 4; t++) {
                        mma_f16(ag[t][j], af[t], bfg);
                        mma_f16(au[t][j], af[t], bfu);
                    }
                }
            }
            __syncthreads();
        }

        // silu(g)*u -> Gs (half2 words)
        #pragma unroll
        for (int t = 0; t < 4; t++) {
            int r0 = t * 16 + gid;
            #pragma unroll
            for (int j = 0; j < 4; j++) {
                int wb = (nb >> 1) + wid * 16 + j * 4 + tig;
                float g0 = ag[t][j][0], g1 = ag[t][j][1];
                float g2 = ag[t][j][2], g3 = ag[t][j][3];
                __half2 h0 = __floats2half2_rn(g0 / (1.f + __expf(-g0)) * au[t][j][0],
                                               g1 / (1.f + __expf(-g1)) * au[t][j][1]);
                __half2 h1 = __floats2half2_rn(g2 / (1.f + __expf(-g2)) * au[t][j][2],
                                               g3 / (1.f + __expf(-g3)) * au[t][j][3]);
                GsW[r0][wb]     = *(uint32_t*)&h0;
                GsW[r0 + 8][wb] = *(uint32_t*)&h1;
            }
        }
    }
    __syncthreads();   // Gs complete before phase2 overwrites Wt / reads Gs

    // ---------- phase 2: down, two out-halves of 512; A = Gs (half) ----------
    #define P2STAGE(buf, k0, ob) do {                                              \
        uint32_t* bd = WtW + (buf) * 10240;                                        \
        _Pragma("unroll")                                                          \
        for (int i = 0; i < 8; i++) {                                              \
            int slot = tid + i * 256;                                              \
            int row = slot >> 2, seg = slot & 3;                                   \
            cp16(cvta_s(bd + row * 20 + seg * 4),                                  \
                 wd16e + (size_t)((ob) + row) * NI + (k0) + seg * 8);              \
        }                                                                          \
    } while (0)

    #pragma unroll 1
    for (int hp = 0; hp < 2; hp++) {
        int ob = hp * 512;
        float acc[4][8][4];
        #pragma unroll
        for (int t = 0; t < 4; t++)
            #pragma unroll
            for (int j = 0; j < 8; j++)
                #pragma unroll
                for (int q = 0; q < 4; q++) acc[t][j][q] = 0.f;

        P2STAGE(0, 0, ob); CP_COMMIT;
        for (int it = 0; it < 16; it++) {
            if (it + 1 < 16) { P2STAGE((it + 1) & 1, (it + 1) << 5, ob); CP_COMMIT; CP_WAIT1; }
            else { CP_WAIT0; }
            __syncthreads();
            const uint32_t* bd = WtW + (it & 1) * 10240;
            int kwb = it * 16;
            #pragma unroll
            for (int kw = 0; kw < 16; kw += 8) {
                uint32_t af[4][4];
                #pragma unroll
                for (int t = 0; t < 4; t++) {
                    int r = t * 16 + gid;
                    af[t][0] = GsW[r][kwb + kw + tig];
                    af[t][1] = GsW[r + 8][kwb + kw + tig];
                    af[t][2] = GsW[r][kwb + kw + 4 + tig];
                    af[t][3] = GsW[r + 8][kwb + kw + 4 + tig];
                }
                #pragma unroll
                for (int j = 0; j < 8; j++) {
                    int n = wid * 64 + j * 8 + gid;
                    uint32_t bf[2];
                    bf[0] = bd[n * 20 + kw + tig];
                    bf[1] = bd[n * 20 + kw + 4 + tig];
                    #pragma unroll
                    for (int t = 0; t < 4; t++) mma_f16(acc[t][j], af[t], bf);
                }
            }
            __syncthreads();
        }

        #pragma unroll
        for (int t = 0; t < 4; t++) {
            int r0 = t * 16 + gid;
            int s0 = slts[r0], s1 = slts[r0 + 8];
            float c0 = scs[r0], c1 = scs[r0 + 8];
            #pragma unroll
            for (int j = 0; j < 8; j++) {
                int c = ob + wid * 64 + j * 8 + 2 * tig;
                if (s0 >= 0)
                    *(float2*)(y + (size_t)s0 * HH + c) =
                        make_float2(c0 * acc[t][j][0], c0 * acc[t][j][1]);
                if (s1 >= 0)
                    *(float2*)(y + (size_t)s1 * HH + c) =
                        make_float2(c1 * acc[t][j][2], c1 * acc[t][j][3]);
            }
        }
    }
    #undef P1STAGE
    #undef P2STAGE
}

// ---------------- gather: out += sum_k y[(n,k)] ----------------
__global__ void gather_k(const float* __restrict__ y, float* __restrict__ out) {
    int n = blockIdx.x;
    int c = threadIdx.x * 4;
    const float* base = y + (size_t)n * TOPK * HH + c;
    float4 a = *(float4*)(out + (size_t)n * HH + c);
    #pragma unroll
    for (int kk = 0; kk < TOPK; kk++) {
        float4 yv = *(const float4*)(base + (size_t)kk * HH);
        a.x += yv.x; a.y += yv.y; a.z += yv.z; a.w += yv.w;
    }
    *(float4*)(out + (size_t)n * HH + c) = a;
}

// ---------------- launch ----------------
extern "C" void kernel_launch(void* const* d_in, const int* in_sizes, int n_in,
                              void* d_out, int out_size) {
    const float* x    = (const float*)d_in[0];
    const float* cosp = (const float*)d_in[1];
    const float* sinp = (const float*)d_in[2];
    const float* ln1w = (const float*)d_in[3];
    const float* ln2w = (const float*)d_in[4];
    const float* Wq   = (const float*)d_in[5];
    const float* Wk   = (const float*)d_in[6];
    const float* Wv   = (const float*)d_in[7];
    const float* Wo   = (const float*)d_in[8];
    const float* Wr   = (const float*)d_in[9];
    const float* Wg   = (const float*)d_in[10];
    const float* Wu   = (const float*)d_in[11];
    const float* Wd   = (const float*)d_in[12];

    float* out    = (float*)d_out;                       // [NTOK, HH]
    float* logits = (float*)d_out + (size_t)NTOK * HH;   // [NTOK, NE]

    float *qb, *kb, *vb, *fb, *yb;
    __half *h16, *f16, *a16, *wq16, *wk16, *wv16, *wo16, *wg16, *wu16, *wd16;
    cudaGetSymbolAddress((void**)&qb, g_q);
    cudaGetSymbolAddress((void**)&kb, g_k);
    cudaGetSymbolAddress((void**)&vb, g_v);
    cudaGetSymbolAddress((void**)&fb, g_f);
    cudaGetSymbolAddress((void**)&yb, g_y);
    cudaGetSymbolAddress((void**)&h16, g_h16);
    cudaGetSymbolAddress((void**)&f16, g_f16);
    cudaGetSymbolAddress((void**)&a16, g_att16);
    cudaGetSymbolAddress((void**)&wq16, g_wq16);
    cudaGetSymbolAddress((void**)&wk16, g_wk16);
    cudaGetSymbolAddress((void**)&wv16, g_wv16);
    cudaGetSymbolAddress((void**)&wo16, g_wo16);
    cudaGetSymbolAddress((void**)&wg16, g_wg16);
    cudaGetSymbolAddress((void**)&wu16, g_wu16);
    cudaGetSymbolAddress((void**)&wd16, g_wd16);

    cudaFuncSetAttribute(moe_mma_k, cudaFuncAttributeMaxDynamicSharedMemorySize, MOE_SMEM);
    cudaFuncSetAttribute(attn_mma_k, cudaFuncAttributeMaxDynamicSharedMemorySize, ATT_SMEM);

    dim3 tb(32, 8);
    // 0. weight transpose-conversions fp32 [k][n] -> half [n][k]
    tconv_k<<<dim3(32, 32, 1), tb>>>(Wq, wq16, 1024, 1024);
    tconv_k<<<dim3(8, 32, 1), tb>>>(Wk, wk16, 1024, 256);
    tconv_k<<<dim3(8, 32, 1), tb>>>(Wv, wv16, 1024, 256);
    tconv_k<<<dim3(32, 32, 1), tb>>>(Wo, wo16, 1024, 1024);
    tconv_k<<<dim3(16, 32, NE), tb>>>(Wg, wg16, 1024, 512);
    tconv_k<<<dim3(16, 32, NE), tb>>>(Wu, wu16, 1024, 512);
    tconv_k<<<dim3(32, 16, NE), tb>>>(Wd, wd16, 512, 1024);

    // 1. rmsnorm1 -> h16
    rmsnorm_k<<<NTOK, 256>>>(x, ln1w, nullptr, h16);
    // 2. fused QKV (fp16 mma) -> fp32 q/k/v
    qkv_mma_k<<<dim3(12, NTOK / 128), 256>>>(h16, wq16, wk16, wv16, qb, kb, vb);
    // 3. RoPE
    {
        int tq = NTOK * NHD * 32;
        rope_k<<<(tq + 255) / 256, 256>>>(qb, cosp, sinp, NHD, tq);
        int tkn = NTOK * NKVH * 32;
        rope_k<<<(tkn + 255) / 256, 256>>>(kb, cosp, sinp, NKVH, tkn);
    }
    // 4. attention (tf32 mma) -> half att
    attn_mma_k<<<dim3(TT / 128, BB * NHD), 256, ATT_SMEM>>>(qb, kb, vb, a16);
    // 5. Wo + residual -> out
    wo_mma_k<<<dim3(HH / 128, NTOK / 128), 256>>>(a16, wo16, x, out);
    // 6. rmsnorm2 -> f (fp32, router) + f16 (MoE)
    rmsnorm_k<<<NTOK, 256>>>(out, ln2w, fb, f16);
    // 7. router logits (fp32)
    sgemm_k<<<dim3(1, NTOK / 64), 256>>>(fb, Wr, logits, NTOK, NE, HH);
    // 8-9. top-8 + scatter
    zero_cnt_k<<<1, 64>>>();
    topk_k<<<(NTOK + 255) / 256, 256>>>(logits);
    // 10. MoE (fp16 mma) -> per-slot scratch
    moe_mma_k<<<dim3(NTOK / MT, NE), 256, MOE_SMEM>>>(f16, wg16, wu16, wd16, yb);
    // 11. gather slots into out
    gather_k<<<NTOK, 256>>>(yb, out);
}

// round 17
// speedup vs baseline: 1.6301x; 1.0341x over previous
#include <cuda_runtime.h>
#include <cuda_fp16.h>
#include <math.h>
#include <stdint.h>

#define BB   2
#define TT   1024
#define HH   1024
#define NHD  16
#define NKVH 4
#define HDD  64
#define NE   64
#define TOPK 8
#define NI   512
#define NTOK (BB*TT)   // 2048
#define MT   64        // MoE token tile

typedef unsigned long long ull;

// ---------------- f32x2 helpers (router) ----------------
__device__ __forceinline__ ull pk2(float a, float b) {
    ull r; asm("mov.b64 %0,{%1,%2};" : "=l"(r) : "f"(a), "f"(b)); return r;
}
__device__ __forceinline__ void fma2(ull& d, ull a, ull b) {
    asm("fma.rn.f32x2 %0,%1,%2,%0;" : "+l"(d) : "l"(a), "l"(b));
}
__device__ __forceinline__ float2 up2(ull v) {
    float2 f; asm("mov.b64 {%0,%1},%2;" : "=f"(f.x), "=f"(f.y) : "l"(v)); return f;
}

// ---------------- mma helpers ----------------
__device__ __forceinline__ void mma_tf32(float* d, const uint32_t* a, const uint32_t* b) {
    asm volatile(
        "mma.sync.aligned.m16n8k8.row.col.f32.tf32.tf32.f32 "
        "{%0,%1,%2,%3}, {%4,%5,%6,%7}, {%8,%9}, {%0,%1,%2,%3};"
        : "+f"(d[0]), "+f"(d[1]), "+f"(d[2]), "+f"(d[3])
        : "r"(a[0]), "r"(a[1]), "r"(a[2]), "r"(a[3]), "r"(b[0]), "r"(b[1]));
}
__device__ __forceinline__ void mma_f16(float* d, const uint32_t* a, const uint32_t* b) {
    asm volatile(
        "mma.sync.aligned.m16n8k16.row.col.f32.f16.f16.f32 "
        "{%0,%1,%2,%3}, {%4,%5,%6,%7}, {%8,%9}, {%0,%1,%2,%3};"
        : "+f"(d[0]), "+f"(d[1]), "+f"(d[2]), "+f"(d[3])
        : "r"(a[0]), "r"(a[1]), "r"(a[2]), "r"(a[3]), "r"(b[0]), "r"(b[1]));
}
__device__ __forceinline__ uint32_t cvta_s(const void* p) {
    return (uint32_t)__cvta_generic_to_shared(p);
}
__device__ __forceinline__ void cp16(uint32_t s, const void* g) {
    asm volatile("cp.async.cg.shared.global [%0], [%1], 16;" :: "r"(s), "l"(g));
}
#define CP_COMMIT asm volatile("cp.async.commit_group;")
#define CP_WAIT0  asm volatile("cp.async.wait_group 0;")
#define CP_WAIT1  asm volatile("cp.async.wait_group 1;")

// ---------------- scratch (device globals) ----------
__device__ float  g_q  [NTOK*NHD*HDD];
__device__ float  g_k  [NTOK*NKVH*HDD];
__device__ float  g_v  [NTOK*NKVH*HDD];
__device__ float  g_f  [NTOK*HH];
__device__ float  g_y  [(size_t)NTOK*TOPK*HH];
__device__ __half g_h16  [NTOK*HH];
__device__ __half g_f16  [NTOK*HH];
__device__ __half g_att16[NTOK*NHD*HDD];
__device__ __half g_wq16[HH*HH];            // transposed [n][k]
__device__ __half g_wk16[HH*NKVH*HDD];
__device__ __half g_wv16[HH*NKVH*HDD];
__device__ __half g_wo16[HH*HH];
__device__ __half g_wg16[(size_t)NE*NI*HH]; // [e][inter][h]
__device__ __half g_wu16[(size_t)NE*NI*HH];
__device__ __half g_wd16[(size_t)NE*HH*NI]; // [e][hout][i]
__device__ int    g_cnt[NE];
__device__ int    g_tok[NE*NTOK];
__device__ float  g_scr[NE*NTOK];
__device__ int    g_slt[NE*NTOK];

// ---------------- fast transpose-convert: out[c][r] = half(in[r][c]) ----------
// 64x64 tiles, float4 loads, half2 coalesced stores. R,C multiples of 64.
__global__ __launch_bounds__(256)
void tconv_k(const float* __restrict__ in, __half* __restrict__ out,
             int R, int C) {
    __shared__ float t[64][65];
    size_t moff = (size_t)blockIdx.z * R * C;
    in += moff; out += moff;
    int c0 = blockIdx.x * 64, r0 = blockIdx.y * 64;
    int tid = threadIdx.x;
    #pragma unroll
    for (int i = 0; i < 4; i++) {
        int idx = tid + i * 256;          // 0..1023 float4 slots
        int r = idx >> 4, c4 = (idx & 15) * 4;
        float4 v = *(const float4*)(in + (size_t)(r0 + r) * C + c0 + c4);
        t[r][c4] = v.x; t[r][c4 + 1] = v.y; t[r][c4 + 2] = v.z; t[r][c4 + 3] = v.w;
    }
    __syncthreads();
    #pragma unroll
    for (int i = 0; i < 8; i++) {
        int idx = tid + i * 256;          // 0..2047 half2 slots
        int cc = idx >> 5, r2 = idx & 31;
        __half2 h = __floats2half2_rn(t[2 * r2][cc], t[2 * r2 + 1][cc]);
        *(__half2*)(out + (size_t)(c0 + cc) * R + r0 + 2 * r2) = h;
    }
}

// ---------------- rmsnorm (fp32 in -> optional fp32 + half out) ----------------
__global__ void rmsnorm_k(const float* __restrict__ x, const float* __restrict__ w,
                          float* __restrict__ o, __half* __restrict__ o16) {
    int row = blockIdx.x;
    const float* xr = x + (size_t)row * HH;
    float ss = 0.f;
    for (int i = threadIdx.x; i < HH; i += 256) { float v = xr[i]; ss += v * v; }
    __shared__ float red[256];
    red[threadIdx.x] = ss; __syncthreads();
    for (int s = 128; s > 0; s >>= 1) {
        if (threadIdx.x < s) red[threadIdx.x] += red[threadIdx.x + s];
        __syncthreads();
    }
    float inv = rsqrtf(red[0] * (1.0f / HH) + 1e-6f);
    for (int i = threadIdx.x; i < HH; i += 256) {
        float v = xr[i] * inv * w[i];
        if (o) o[(size_t)row * HH + i] = v;
        o16[(size_t)row * HH + i] = __float2half(v);
    }
}

// ======== 128x128 fp16 MMA GEMM core (A [m][K], B transposed [n][K]) ========
__device__ __forceinline__ void stageABh(int tid, int buf, int k0,
    const __half* __restrict__ Ab, const __half* __restrict__ Bb, int K,
    uint32_t (*Ah)[128][20], uint32_t (*Bh)[128][20]) {
    #pragma unroll
    for (int i = 0; i < 2; i++) {
        int slot = tid + i * 256;
        int row = slot >> 2, seg = slot & 3;
        cp16(cvta_s(&Ah[buf][row][seg * 4]), Ab + (size_t)row * K + k0 + seg * 8);
    }
    #pragma unroll
    for (int i = 0; i < 2; i++) {
        int slot = tid + i * 256;
        int row = slot >> 2, seg = slot & 3;
        cp16(cvta_s(&Bh[buf][row][seg * 4]), Bb + (size_t)row * K + k0 + seg * 8);
    }
}

__device__ __forceinline__ void gemm128h(
    const __half* __restrict__ Ab, const __half* __restrict__ Bb, int K,
    uint32_t (*Ah)[128][20], uint32_t (*Bh)[128][20],
    float acc[2][8][4], int tid)
{
    int lane = tid & 31, wid = tid >> 5;
    int wm = (wid & 3) * 32, wn = (wid >> 2) * 64;
    int gid = lane >> 2, tig = lane & 3;

    stageABh(tid, 0, 0, Ab, Bb, K, Ah, Bh);
    CP_COMMIT;
    int nit = K >> 5;
    for (int it = 0; it < nit; it++) {
        if (it + 1 < nit) {
            stageABh(tid, (it + 1) & 1, (it + 1) << 5, Ab, Bb, K, Ah, Bh);
            CP_COMMIT; CP_WAIT1;
        } else { CP_WAIT0; }
        __syncthreads();
        const uint32_t (*A1)[20] = Ah[it & 1];
        const uint32_t (*B1)[20] = Bh[it & 1];
        #pragma unroll
        for (int kw = 0; kw < 16; kw += 8) {
            uint32_t af[2][4];
            #pragma unroll
            for (int t = 0; t < 2; t++) {
                int r = wm + t * 16 + gid;
                af[t][0] = A1[r][kw + tig];
                af[t][1] = A1[r + 8][kw + tig];
                af[t][2] = A1[r][kw + 4 + tig];
                af[t][3] = A1[r + 8][kw + 4 + tig];
            }
            #pragma unroll
            for (int j = 0; j < 8; j++) {
                int n = wn + j * 8 + gid;
                uint32_t bf[2];
                bf[0] = B1[n][kw + tig];
                bf[1] = B1[n][kw + 4 + tig];
                mma_f16(acc[0][j], af[0], bf);
                mma_f16(acc[1][j], af[1], bf);
            }
        }
        __syncthreads();
    }
}

// ---------------- fused QKV (fp16 mma) + in-register RoPE ----------------
__global__ __launch_bounds__(256)
void qkv_mma_k(const __half* __restrict__ A,
               const __half* __restrict__ Wq, const __half* __restrict__ Wk,
               const __half* __restrict__ Wv,
               const float* __restrict__ cosp, const float* __restrict__ sinp,
               float* __restrict__ qo, float* __restrict__ ko, float* __restrict__ vo) {
    __shared__ __align__(16) uint32_t Ah[2][128][20];
    __shared__ __align__(16) uint32_t Bh[2][128][20];
    int bx = blockIdx.x;
    const __half* Bp; float* O; int N, colb;
    if (bx < 8)       { Bp = Wq; O = qo; N = 1024; colb = bx * 128; }
    else if (bx < 10) { Bp = Wk; O = ko; N = 256;  colb = (bx - 8)  * 128; }
    else              { Bp = Wv; O = vo; N = 256;  colb = (bx - 10) * 128; }
    bool rope = (bx < 10);

    int tid = threadIdx.x, lane = tid & 31, wid = tid >> 5;
    int wm = (wid & 3) * 32, wn = (wid >> 2) * 64;
    int gid = lane >> 2, tig = lane & 3;
    int mbase = blockIdx.y * 128;
    float acc[2][8][4];
    #pragma unroll
    for (int t = 0; t < 2; t++)
        #pragma unroll
        for (int j = 0; j < 8; j++)
            #pragma unroll
            for (int q = 0; q < 4; q++) acc[t][j][q] = 0.f;

    gemm128h(A + (size_t)mbase * HH, Bp + (size_t)colb * HH, HH, Ah, Bh, acc, tid);

    #pragma unroll
    for (int t = 0; t < 2; t++) {
        int r0 = mbase + wm + t * 16 + gid;
        int tk0 = r0 & (TT - 1), tk1 = (r0 + 8) & (TT - 1);
        #pragma unroll
        for (int j = 0; j < 8; j++) {
            int c = colb + wn + j * 8 + 2 * tig;
            float v0 = acc[t][j][0], v1 = acc[t][j][1];
            float v2 = acc[t][j][2], v3 = acc[t][j][3];
            if (rope) {
                int d = c & 63;
                float p0 = acc[t][j ^ 4][0], p1 = acc[t][j ^ 4][1];
                float p2 = acc[t][j ^ 4][2], p3 = acc[t][j ^ 4][3];
                float c00 = cosp[tk0 * HDD + d], c01 = cosp[tk0 * HDD + d + 1];
                float s00 = sinp[tk0 * HDD + d], s01 = sinp[tk0 * HDD + d + 1];
                float c10 = cosp[tk1 * HDD + d], c11 = cosp[tk1 * HDD + d + 1];
                float s10 = sinp[tk1 * HDD + d], s11 = sinp[tk1 * HDD + d + 1];
                if (d < 32) {
                    v0 = v0 * c00 - p0 * s00; v1 = v1 * c01 - p1 * s01;
                    v2 = v2 * c10 - p2 * s10; v3 = v3 * c11 - p3 * s11;
                } else {
                    v0 = v0 * c00 + p0 * s00; v1 = v1 * c01 + p1 * s01;
                    v2 = v2 * c10 + p2 * s10; v3 = v3 * c11 + p3 * s11;
                }
            }
            *(float2*)(O + (size_t)r0 * N + c)       = make_float2(v0, v1);
            *(float2*)(O + (size_t)(r0 + 8) * N + c) = make_float2(v2, v3);
        }
    }
}

// ---------------- Wo GEMM + residual (fp16 mma) ----------------
__global__ __launch_bounds__(256)
void wo_mma_k(const __half* __restrict__ A, const __half* __restrict__ B,
              const float* __restrict__ R, float* __restrict__ C) {
    __shared__ __align__(16) uint32_t Ah[2][128][20];
    __shared__ __align__(16) uint32_t Bh[2][128][20];
    int tid = threadIdx.x, lane = tid & 31, wid = tid >> 5;
    int wm = (wid & 3) * 32, wn = (wid >> 2) * 64;
    int mbase = blockIdx.y * 128, nbase = blockIdx.x * 128;
    float acc[2][8][4];
    #pragma unroll
    for (int t = 0; t < 2; t++)
        #pragma unroll
        for (int j = 0; j < 8; j++)
            #pragma unroll
            for (int q = 0; q < 4; q++) acc[t][j][q] = 0.f;

    gemm128h(A + (size_t)mbase * HH, B + (size_t)nbase * HH, HH, Ah, Bh, acc, tid);

    #pragma unroll
    for (int t = 0; t < 2; t++) {
        int r0 = mbase + wm + t * 16 + (lane >> 2);
        #pragma unroll
        for (int j = 0; j < 8; j++) {
            int c = nbase + wn + j * 8 + 2 * (lane & 3);
            float2 x0 = *(const float2*)(R + (size_t)r0 * HH + c);
            float2 x1 = *(const float2*)(R + (size_t)(r0 + 8) * HH + c);
            *(float2*)(C + (size_t)r0 * HH + c) =
                make_float2(acc[t][j][0] + x0.x, acc[t][j][1] + x0.y);
            *(float2*)(C + (size_t)(r0 + 8) * HH + c) =
                make_float2(acc[t][j][2] + x1.x, acc[t][j][3] + x1.y);
        }
    }
}

// ======== flash attention, tf32 mma (output stored as half) ========
#define ATT_SMEM ((17664 + 8704) * 4)

__global__ __launch_bounds__(256, 1)
void attn_mma_k(const float* __restrict__ q, const float* __restrict__ k,
                const float* __restrict__ v, __half* __restrict__ o16) {
    extern __shared__ float sm[];
    float (*Qs)[68] = (float(*)[68])sm;
    float (*Ks)[68] = (float(*)[68])(sm + 8704);
    float (*Vs)[72] = (float(*)[72])(sm + 13056);
    float (*Ps)[68] = (float(*)[68])(sm + 17664);

    int bh = blockIdx.y;
    int b = bh >> 4, h = bh & 15, kvh = h >> 2;
    int bx = blockIdx.x;
    int tid = threadIdx.x, lane = tid & 31, wq = tid >> 5;
    int gid = lane >> 2, tig = lane & 3;

    for (int i = tid; i < 128 * 16; i += 256) {
        int r = i >> 4, d4 = (i & 15) * 4;
        float4 val = *(const float4*)(q + (((size_t)(b * TT + bx * 128 + r)) * NHD + h) * HDD + d4);
        val.x *= 0.125f; val.y *= 0.125f; val.z *= 0.125f; val.w *= 0.125f;
        *(float4*)&Qs[r][d4] = val;
    }

    float o_acc[8][4];
    #pragma unroll
    for (int j = 0; j < 8; j++)
        #pragma unroll
        for (int qq = 0; qq < 4; qq++) o_acc[j][qq] = 0.f;
    float m0 = -1e30f, m1 = -1e30f, l0 = 0.f, l1 = 0.f;

    int r0g = bx * 128 + wq * 16 + gid;
    int r1g = r0g + 8;
    float (*Psw)[68] = Ps + wq * 16;

    int kv_end = (bx + 1) * 128;
    for (int j0 = 0; j0 < kv_end; j0 += 64) {
        __syncthreads();
        for (int i = tid; i < 64 * 16; i += 256) {
            int r = i >> 4, d4 = (i & 15) * 4;
            size_t base = (((size_t)(b * TT + j0 + r)) * NKVH + kvh) * HDD + d4;
            *(float4*)&Ks[r][d4] = *(const float4*)(k + base);
            *(float4*)&Vs[r][d4] = *(const float4*)(v + base);
        }
        __syncthreads();

        float s[8][4];
        #pragma unroll
        for (int j = 0; j < 8; j++)
            #pragma unroll
            for (int qq = 0; qq < 4; qq++) s[j][qq] = 0.f;
        #pragma unroll
        for (int k8 = 0; k8 < 64; k8 += 8) {
            int kk = k8 + tig;
            uint32_t af[4];
            int r = wq * 16 + gid;
            af[0] = __float_as_uint(Qs[r][kk]);
            af[1] = __float_as_uint(Qs[r + 8][kk]);
            af[2] = __float_as_uint(Qs[r][kk + 4]);
            af[3] = __float_as_uint(Qs[r + 8][kk + 4]);
            #pragma unroll
            for (int j = 0; j < 8; j++) {
                int n = j * 8 + gid;
                uint32_t bf[2];
                bf[0] = __float_as_uint(Ks[n][kk]);
                bf[1] = __float_as_uint(Ks[n][kk + 4]);
                mma_tf32(s[j], af, bf);
            }
        }

        if (j0 + 63 > r0g) {
            #pragma unroll
            for (int j = 0; j < 8; j++) {
                int cg = j0 + j * 8 + 2 * tig;
                if (cg > r0g)     s[j][0] = -1e30f;
                if (cg + 1 > r0g) s[j][1] = -1e30f;
            }
        }
        if (j0 + 63 > r1g) {
            #pragma unroll
            for (int j = 0; j < 8; j++) {
                int cg = j0 + j * 8 + 2 * tig;
                if (cg > r1g)     s[j][2] = -1e30f;
                if (cg + 1 > r1g) s[j][3] = -1e30f;
            }
        }

        float rm0 = -1e30f, rm1 = -1e30f;
        #pragma unroll
        for (int j = 0; j < 8; j++) {
            rm0 = fmaxf(rm0, fmaxf(s[j][0], s[j][1]));
            rm1 = fmaxf(rm1, fmaxf(s[j][2], s[j][3]));
        }
        #pragma unroll
        for (int off = 1; off <= 2; off <<= 1) {
            rm0 = fmaxf(rm0, __shfl_xor_sync(0xffffffff, rm0, off));
            rm1 = fmaxf(rm1, __shfl_xor_sync(0xffffffff, rm1, off));
        }
        float mn0 = fmaxf(m0, rm0), mn1 = fmaxf(m1, rm1);
        float sc0 = __expf(m0 - mn0), sc1 = __expf(m1 - mn1);
        m0 = mn0; m1 = mn1;

        float rs0 = 0.f, rs1 = 0.f;
        float p[8][4];
        #pragma unroll
        for (int j = 0; j < 8; j++) {
            p[j][0] = __expf(s[j][0] - mn0);
            p[j][1] = __expf(s[j][1] - mn0);
            p[j][2] = __expf(s[j][2] - mn1);
            p[j][3] = __expf(s[j][3] - mn1);
            rs0 += p[j][0] + p[j][1];
            rs1 += p[j][2] + p[j][3];
        }
        #pragma unroll
        for (int off = 1; off <= 2; off <<= 1) {
            rs0 += __shfl_xor_sync(0xffffffff, rs0, off);
            rs1 += __shfl_xor_sync(0xffffffff, rs1, off);
        }
        l0 = l0 * sc0 + rs0;
        l1 = l1 * sc1 + rs1;

        #pragma unroll
        for (int j = 0; j < 8; j++) {
            o_acc[j][0] *= sc0; o_acc[j][1] *= sc0;
            o_acc[j][2] *= sc1; o_acc[j][3] *= sc1;
        }

        #pragma unroll
        for (int j = 0; j < 8; j++) {
            int c = j * 8 + 2 * tig;
            Psw[gid][c]         = p[j][0];
            Psw[gid][c + 1]     = p[j][1];
            Psw[gid + 8][c]     = p[j][2];
            Psw[gid + 8][c + 1] = p[j][3];
        }
        __syncwarp();

        #pragma unroll
        for (int k8 = 0; k8 < 64; k8 += 8) {
            int kk = k8 + tig;
            uint32_t af[4];
            af[0] = __float_as_uint(Psw[gid][kk]);
            af[1] = __float_as_uint(Psw[gid + 8][kk]);
            af[2] = __float_as_uint(Psw[gid][kk + 4]);
            af[3] = __float_as_uint(Psw[gid + 8][kk + 4]);
            #pragma unroll
            for (int j = 0; j < 8; j++) {
                int n = j * 8 + gid;
                uint32_t bf[2];
                bf[0] = __float_as_uint(Vs[kk][n]);
                bf[1] = __float_as_uint(Vs[kk + 4][n]);
                mma_tf32(o_acc[j], af, bf);
            }
        }
    }

    float i0 = 1.f / l0, i1 = 1.f / l1;
    #pragma unroll
    for (int j = 0; j < 8; j++) {
        int c = j * 8 + 2 * tig;
        *(__half2*)(o16 + (((size_t)(b * TT + r0g)) * NHD + h) * HDD + c) =
            __floats2half2_rn(o_acc[j][0] * i0, o_acc[j][1] * i0);
        *(__half2*)(o16 + (((size_t)(b * TT + r1g)) * NHD + h) * HDD + c) =
            __floats2half2_rn(o_acc[j][2] * i1, o_acc[j][3] * i1);
    }
}

// ---------------- router SGEMM (fp32, N=64) ----------------
__global__ __launch_bounds__(256)
void sgemm_k(const float* __restrict__ A, const float* __restrict__ B,
             float* __restrict__ C, int M, int N, int K) {
    __shared__ ull   As2[16][64];
    __shared__ float Bs[16][64];
    int tid = threadIdx.x;
    int tx = tid & 15, ty = tid >> 4;
    const float* Ab = A + (size_t)blockIdx.y * 64 * K;
    const float* Bb = B + (size_t)blockIdx.x * 64;
    ull acc[4][2];
    #pragma unroll
    for (int i = 0; i < 4; i++) { acc[i][0] = 0ull; acc[i][1] = 0ull; }

    for (int k0 = 0; k0 < K; k0 += 16) {
        #pragma unroll
        for (int l = 0; l < 4; l++) {
            int idx = tid + l * 256;
            int m = idx >> 4, kk = idx & 15;
            float vv = Ab[(size_t)m * K + k0 + kk];
            As2[kk][m] = pk2(vv, vv);
        }
        #pragma unroll
        for (int l = 0; l < 4; l++) {
            int idx = tid + l * 256;
            int kk = idx >> 6, n = idx & 63;
            Bs[kk][n] = Bb[(size_t)(k0 + kk) * N + n];
        }
        __syncthreads();
        #pragma unroll
        for (int kk = 0; kk < 16; kk++) {
            const ull* brow = (const ull*)Bs[kk];
            ull b0 = brow[tx * 2], b1 = brow[tx * 2 + 1];
            #pragma unroll
            for (int i = 0; i < 4; i++) {
                ull a2 = As2[kk][ty * 4 + i];
                fma2(acc[i][0], a2, b0);
                fma2(acc[i][1], a2, b1);
            }
        }
        __syncthreads();
    }
    #pragma unroll
    for (int i = 0; i < 4; i++) {
        int m = blockIdx.y * 64 + ty * 4 + i;
        int nb = blockIdx.x * 64 + tx * 4;
        float2 c0 = up2(acc[i][0]), c1 = up2(acc[i][1]);
        *(float4*)(C + (size_t)m * N + nb) = make_float4(c0.x, c0.y, c1.x, c1.y);
    }
}

// ---------------- router top-8 select + expert scatter ----------------
__global__ void zero_cnt_k() {
    if (threadIdx.x < NE) g_cnt[threadIdx.x] = 0;
}

__global__ void topk_k(const float* __restrict__ logits) {
    int n = blockIdx.x * blockDim.x + threadIdx.x;
    if (n >= NTOK) return;
    float lg[NE];
    for (int e = 0; e < NE; e++) lg[e] = logits[(size_t)n * NE + e];
    int   ids[TOPK];
    float vals[TOPK];
    for (int kk = 0; kk < TOPK; kk++) {
        int best = 0; float bv = lg[0];
        for (int e = 1; e < NE; e++) if (lg[e] > bv) { bv = lg[e]; best = e; }
        ids[kk] = best; vals[kk] = bv; lg[best] = -1e30f;
    }
    float mx = vals[0], sum = 0.f;
    for (int kk = 0; kk < TOPK; kk++) { vals[kk] = __expf(vals[kk] - mx); sum += vals[kk]; }
    float inv = 1.f / sum;
    for (int kk = 0; kk < TOPK; kk++) {
        int e = ids[kk];
        int p = atomicAdd(&g_cnt[e], 1);
        g_tok[e * NTOK + p] = n;
        g_scr[e * NTOK + p] = vals[kk] * inv;
        g_slt[e * NTOK + p] = n * TOPK + kk;
    }
}

// ======== MoE: fp16 mma, 64-token tiles ========
#define MOE_SMEM (39872 * 4 + 256)

__global__ __launch_bounds__(256, 1)
void moe_mma_k(const __half* __restrict__ f16, const __half* __restrict__ Wg,
               const __half* __restrict__ Wu, const __half* __restrict__ Wd,
               float* __restrict__ y) {
    extern __shared__ uint32_t smw[];
    uint32_t (*AstW)[20] = (uint32_t(*)[20])smw;
    uint32_t (*GsW)[260] = (uint32_t(*)[260])(smw + 2560);
    uint32_t* WtW        = smw + 19200;
    int*   toks = (int*)(smw + 39680);
    float* scs  = (float*)(smw + 39744);
    int*   slts = (int*)(smw + 39808);

    int e  = blockIdx.y;
    int nt = g_cnt[e];
    int t0 = blockIdx.x * MT;
    if (t0 >= nt) return;

    int tid = threadIdx.x, lane = tid & 31, wid = tid >> 5;
    int gid = lane >> 2, tig = lane & 3;
    if (tid < MT) {
        int ti = t0 + tid;
        toks[tid] = (ti < nt) ? g_tok[e * NTOK + ti] : 0;
        scs[tid]  = (ti < nt) ? g_scr[e * NTOK + ti] : 0.f;
        slts[tid] = (ti < nt) ? g_slt[e * NTOK + ti] : -1;
    }
    __syncthreads();

    const __half* wg16e = Wg + (size_t)e * NI * HH;
    const __half* wu16e = Wu + (size_t)e * NI * HH;
    const __half* wd16e = Wd + (size_t)e * HH * NI;

    #define P1STAGE(buf, k0, nb) do {                                              \
        {   int row = tid >> 2, seg = tid & 3;                                     \
            cp16(cvta_s(&AstW[(buf) * 64 + row][seg * 4]),                         \
                 f16 + (size_t)toks[row] * HH + (k0) + seg * 8); }                 \
        uint32_t* bg = WtW + (buf) * 10240;                                        \
        uint32_t* bu = bg + 5120;                                                  \
        _Pragma("unroll")                                                          \
        for (int i = 0; i < 4; i++) {                                              \
            int slot = tid + i * 256;                                              \
            int row = slot >> 2, seg = slot & 3;                                   \
            cp16(cvta_s(bg + row * 20 + seg * 4),                                  \
                 wg16e + (size_t)((nb) + row) * HH + (k0) + seg * 8);              \
            cp16(cvta_s(bu + row * 20 + seg * 4),                                  \
                 wu16e + (size_t)((nb) + row) * HH + (k0) + seg * 8);              \
        }                                                                          \
    } while (0)

    #pragma unroll 1
    for (int half = 0; half < 2; half++) {
        int nb = half * 256;
        float ag[4][4][4], au[4][4][4];
        #pragma unroll
        for (int t = 0; t < 4; t++)
            #pragma unroll
            for (int j = 0; j < 4; j++)
                #pragma unroll
                for (int q = 0; q < 4; q++) { ag[t][j][q] = 0.f; au[t][j][q] = 0.f; }

        P1STAGE(0, 0, nb); CP_COMMIT;
        for (int it = 0; it < 32; it++) {
            if (it + 1 < 32) { P1STAGE((it + 1) & 1, (it + 1) << 5, nb); CP_COMMIT; CP_WAIT1; }
            else { CP_WAIT0; }
            __syncthreads();
            const uint32_t (*A1)[20] = AstW + (it & 1) * 64;
            const uint32_t* bg = WtW + (it & 1) * 10240;
            const uint32_t* bu = bg + 5120;
            #pragma unroll
            for (int kw = 0; kw < 16; kw += 8) {
                uint32_t af[4][4];
                #pragma unroll
                for (int t = 0; t < 4; t++) {
                    int r = t * 16 + gid;
                    af[t][0] = A1[r][kw + tig];
                    af[t][1] = A1[r + 8][kw + tig];
                    af[t][2] = A1[r][kw + 4 + tig];
                    af[t][3] = A1[r + 8][kw + 4 + tig];
                }
                #pragma unroll
                for (int j = 0; j < 4; j++) {
                    int n = wid * 32 + j * 8 + gid;
                    uint32_t bfg[2], bfu[2];
                    bfg[0] = bg[n * 20 + kw + tig];
                    bfg[1] = bg[n * 20 + kw + 4 + tig];
                    bfu[0] = bu[n * 20 + kw + tig];
                    bfu[1] = bu[n * 20 + kw + 4 + tig];
                    #pragma unroll
                    for (int t = 0; t < 4; t++) {
                        mma_f16(ag[t][j], af[t], bfg);
                        mma_f16(au[t][j], af[t], bfu);
                    }
                }
            }
            __syncthreads();
        }

        #pragma unroll
        for (int t = 0; t < 4; t++) {
            int r0 = t * 16 + gid;
            #pragma unroll
            for (int j = 0; j < 4; j++) {
                int wb = (nb >> 1) + wid * 16 + j * 4 + tig;
                float g0 = ag[t][j][0], g1 = ag[t][j][1];
                float g2 = ag[t][j][2], g3 = ag[t][j][3];
                __half2 h0 = __floats2half2_rn(g0 / (1.f + __expf(-g0)) * au[t][j][0],
                                               g1 / (1.f + __expf(-g1)) * au[t][j][1]);
                __half2 h1 = __floats2half2_rn(g2 / (1.f + __expf(-g2)) * au[t][j][2],
                                               g3 / (1.f + __expf(-g3)) * au[t][j][3]);
                GsW[r0][wb]     = *(uint32_t*)&h0;
                GsW[r0 + 8][wb] = *(uint32_t*)&h1;
            }
        }
    }
    __syncthreads();

    #define P2STAGE(buf, k0, ob) do {                                              \
        uint32_t* bd = WtW + (buf) * 10240;                                        \
        _Pragma("unroll")                                                          \
        for (int i = 0; i < 8; i++) {                                              \
            int slot = tid + i * 256;                                              \
            int row = slot >> 2, seg = slot & 3;                                   \
            cp16(cvta_s(bd + row * 20 + seg * 4),                                  \
                 wd16e + (size_t)((ob) + row) * NI + (k0) + seg * 8);              \
        }                                                                          \
    } while (0)

    #pragma unroll 1
    for (int hp = 0; hp < 2; hp++) {
        int ob = hp * 512;
        float acc[4][8][4];
        #pragma unroll
        for (int t = 0; t < 4; t++)
            #pragma unroll
            for (int j = 0; j < 8; j++)
                #pragma unroll
                for (int q = 0; q < 4; q++) acc[t][j][q] = 0.f;

        P2STAGE(0, 0, ob); CP_COMMIT;
        for (int it = 0; it < 16; it++) {
            if (it + 1 < 16) { P2STAGE((it + 1) & 1, (it + 1) << 5, ob); CP_COMMIT; CP_WAIT1; }
            else { CP_WAIT0; }
            __syncthreads();
            const uint32_t* bd = WtW + (it & 1) * 10240;
            int kwb = it * 16;
            #pragma unroll
            for (int kw = 0; kw < 16; kw += 8) {
                uint32_t af[4][4];
                #pragma unroll
                for (int t = 0; t < 4; t++) {
                    int r = t * 16 + gid;
                    af[t][0] = GsW[r][kwb + kw + tig];
                    af[t][1] = GsW[r + 8][kwb + kw + tig];
                    af[t][2] = GsW[r][kwb + kw + 4 + tig];
                    af[t][3] = GsW[r + 8][kwb + kw + 4 + tig];
                }
                #pragma unroll
                for (int j = 0; j < 8; j++) {
                    int n = wid * 64 + j * 8 + gid;
                    uint32_t bf[2];
                    bf[0] = bd[n * 20 + kw + tig];
                    bf[1] = bd[n * 20 + kw + 4 + tig];
                    #pragma unroll
                    for (int t = 0; t < 4; t++) mma_f16(acc[t][j], af[t], bf);
                }
            }
            __syncthreads();
        }

        #pragma unroll
        for (int t = 0; t < 4; t++) {
            int r0 = t * 16 + gid;
            int s0 = slts[r0], s1 = slts[r0 + 8];
            float c0 = scs[r0], c1 = scs[r0 + 8];
            #pragma unroll
            for (int j = 0; j < 8; j++) {
                int c = ob + wid * 64 + j * 8 + 2 * tig;
                if (s0 >= 0)
                    *(float2*)(y + (size_t)s0 * HH + c) =
                        make_float2(c0 * acc[t][j][0], c0 * acc[t][j][1]);
                if (s1 >= 0)
                    *(float2*)(y + (size_t)s1 * HH + c) =
                        make_float2(c1 * acc[t][j][2], c1 * acc[t][j][3]);
            }
        }
    }
    #undef P1STAGE
    #undef P2STAGE
}

// ---------------- gather: out += sum_k y[(n,k)] ----------------
__global__ void gather_k(const float* __restrict__ y, float* __restrict__ out) {
    int n = blockIdx.x;
    int c = threadIdx.x * 4;
    const float* base = y + (size_t)n * TOPK * HH + c;
    float4 a = *(float4*)(out + (size_t)n * HH + c);
    #pragma unroll
    for (int kk = 0; kk < TOPK; kk++) {
        float4 yv = *(const float4*)(base + (size_t)kk * HH);
        a.x += yv.x; a.y += yv.y; a.z += yv.z; a.w += yv.w;
    }
    *(float4*)(out + (size_t)n * HH + c) = a;
}

// ---------------- launch ----------------
extern "C" void kernel_launch(void* const* d_in, const int* in_sizes, int n_in,
                              void* d_out, int out_size) {
    const float* x    = (const float*)d_in[0];
    const float* cosp = (const float*)d_in[1];
    const float* sinp = (const float*)d_in[2];
    const float* ln1w = (const float*)d_in[3];
    const float* ln2w = (const float*)d_in[4];
    const float* Wq   = (const float*)d_in[5];
    const float* Wk   = (const float*)d_in[6];
    const float* Wv   = (const float*)d_in[7];
    const float* Wo   = (const float*)d_in[8];
    const float* Wr   = (const float*)d_in[9];
    const float* Wg   = (const float*)d_in[10];
    const float* Wu   = (const float*)d_in[11];
    const float* Wd   = (const float*)d_in[12];

    float* out    = (float*)d_out;                       // [NTOK, HH]
    float* logits = (float*)d_out + (size_t)NTOK * HH;   // [NTOK, NE]

    float *qb, *kb, *vb, *fb, *yb;
    __half *h16, *f16, *a16, *wq16, *wk16, *wv16, *wo16, *wg16, *wu16, *wd16;
    cudaGetSymbolAddress((void**)&qb, g_q);
    cudaGetSymbolAddress((void**)&kb, g_k);
    cudaGetSymbolAddress((void**)&vb, g_v);
    cudaGetSymbolAddress((void**)&fb, g_f);
    cudaGetSymbolAddress((void**)&yb, g_y);
    cudaGetSymbolAddress((void**)&h16, g_h16);
    cudaGetSymbolAddress((void**)&f16, g_f16);
    cudaGetSymbolAddress((void**)&a16, g_att16);
    cudaGetSymbolAddress((void**)&wq16, g_wq16);
    cudaGetSymbolAddress((void**)&wk16, g_wk16);
    cudaGetSymbolAddress((void**)&wv16, g_wv16);
    cudaGetSymbolAddress((void**)&wo16, g_wo16);
    cudaGetSymbolAddress((void**)&wg16, g_wg16);
    cudaGetSymbolAddress((void**)&wu16, g_wu16);
    cudaGetSymbolAddress((void**)&wd16, g_wd16);

    cudaFuncSetAttribute(moe_mma_k, cudaFuncAttributeMaxDynamicSharedMemorySize, MOE_SMEM);
    cudaFuncSetAttribute(attn_mma_k, cudaFuncAttributeMaxDynamicSharedMemorySize, ATT_SMEM);

    // 0. weight transpose-conversions fp32 [k][n] -> half [n][k] (64x64 tiles)
    tconv_k<<<dim3(16, 16, 1), 256>>>(Wq, wq16, 1024, 1024);
    tconv_k<<<dim3(4, 16, 1), 256>>>(Wk, wk16, 1024, 256);
    tconv_k<<<dim3(4, 16, 1), 256>>>(Wv, wv16, 1024, 256);
    tconv_k<<<dim3(16, 16, 1), 256>>>(Wo, wo16, 1024, 1024);
    tconv_k<<<dim3(8, 16, NE), 256>>>(Wg, wg16, 1024, 512);
    tconv_k<<<dim3(8, 16, NE), 256>>>(Wu, wu16, 1024, 512);
    tconv_k<<<dim3(16, 8, NE), 256>>>(Wd, wd16, 512, 1024);

    // 1. rmsnorm1 -> h16
    rmsnorm_k<<<NTOK, 256>>>(x, ln1w, nullptr, h16);
    // 2. fused QKV (fp16 mma) + in-register RoPE -> fp32 q/k/v
    qkv_mma_k<<<dim3(12, NTOK / 128), 256>>>(h16, wq16, wk16, wv16, cosp, sinp, qb, kb, vb);
    // 3. attention (tf32 mma) -> half att
    attn_mma_k<<<dim3(TT / 128, BB * NHD), 256, ATT_SMEM>>>(qb, kb, vb, a16);
    // 4. Wo + residual -> out
    wo_mma_k<<<dim3(HH / 128, NTOK / 128), 256>>>(a16, wo16, x, out);
    // 5. rmsnorm2 -> f (fp32, router) + f16 (MoE)
    rmsnorm_k<<<NTOK, 256>>>(out, ln2w, fb, f16);
    // 6. router logits (fp32)
    sgemm_k<<<dim3(1, NTOK / 64), 256>>>(fb, Wr, logits, NTOK, NE, HH);
    // 7-8. top-8 + scatter
    zero_cnt_k<<<1, 64>>>();
    topk_k<<<(NTOK + 255) / 256, 256>>>(logits);
    // 9. MoE (fp16 mma) -> per-slot scratch
    moe_mma_k<<<dim3(NTOK / MT, NE), 256, MOE_SMEM>>>(f16, wg16, wu16, wd16, yb);
    // 10. gather slots into out
    gather_k<<<NTOK, 256>>>(yb, out);
}